// round 1
// baseline (speedup 1.0000x reference)
#include <cuda_runtime.h>
#include <math.h>

#define NIN  1024   // n_in
#define KDIM 1024   // K (codebook entries / logit width)
#define EDIM 256    // embedding dim
#define BM   32     // rows per block
#define NTHREADS 256

// scratch for cross-block avg_p accumulation (allowed: __device__ global)
__device__ float g_avgp[KDIM];

__global__ void zero_avgp_kernel() {
    int i = blockIdx.x * blockDim.x + threadIdx.x;
    if (i < KDIM) g_avgp[i] = 0.0f;
}

extern __shared__ float smem_dyn[];

// Fused: logits GEMM (fp32) + bias + gumbel + argmax + softmax-sum +
//        avg_p accumulation + codebook gather + m output.
__global__ __launch_bounds__(NTHREADS, 1)
void fused_vq_kernel(const float* __restrict__ x,      // [B, NIN]
                     const float* __restrict__ gum,    // [B, KDIM]
                     const float* __restrict__ W,      // [KDIM, NIN]
                     const float* __restrict__ bias,   // [KDIM]
                     const float* __restrict__ cb,     // [KDIM, EDIM]
                     float* __restrict__ out,          // z_q | m | div | 0
                     int B)
{
    float* ws = smem_dyn;               // [32 ki][1024 ko], XOR-swizzled quads
    float* xs = smem_dyn + 32 * 1024;   // [32 ki][32 row]

    __shared__ float swmax[8];
    __shared__ int   swarg[8];
    __shared__ float swsum[8];
    __shared__ int   srowarg[BM];

    const int tid = threadIdx.x;
    const int rg  = tid >> 6;    // 0..3  -> rows rg*8 .. rg*8+7
    const int cg  = tid & 63;    // 0..63 -> cols cg*4 + g*256 + j
    const int rowbase = blockIdx.x * BM;

    float acc[8][16];
    #pragma unroll
    for (int r = 0; r < 8; r++)
        #pragma unroll
        for (int c = 0; c < 16; c++) acc[r][c] = 0.0f;

    const int lrow = tid >> 3;   // 0..31 (x-tile loads)
    const int lkiv = tid & 7;    // 0..7
    const int lb   = tid & 7;    // W-tile: ki quad
    const int lat  = tid >> 3;   // W-tile: base of ko quad

    // ---------------- GEMM main loop ----------------
    for (int kk = 0; kk < NIN; kk += 32) {
        // x tile: [32 rows][32 ki] -> xs[ki][row]
        {
            float4 xv = *(const float4*)(x + (size_t)(rowbase + lrow) * NIN + kk + lkiv * 4);
            xs[(lkiv * 4 + 0) * 32 + lrow] = xv.x;
            xs[(lkiv * 4 + 1) * 32 + lrow] = xv.y;
            xs[(lkiv * 4 + 2) * 32 + lrow] = xv.z;
            xs[(lkiv * 4 + 3) * 32 + lrow] = xv.w;
        }
        // W tile: [1024 ko][32 ki] -> ws[ki][ko] via 4x4 register transpose,
        // stored with quad swizzle (a ^ b) for conflict-free STS128/LDS128.
        #pragma unroll
        for (int i = 0; i < 8; i++) {
            int a = i * 32 + lat;          // ko quad 0..255
            const float* wp = W + (size_t)(a * 4) * NIN + kk + lb * 4;
            float4 w0 = *(const float4*)(wp);
            float4 w1 = *(const float4*)(wp + NIN);
            float4 w2 = *(const float4*)(wp + 2 * NIN);
            float4 w3 = *(const float4*)(wp + 3 * NIN);
            float* dst = ws + (lb * 4) * 1024 + ((a ^ lb) << 2);
            *(float4*)(dst)        = make_float4(w0.x, w1.x, w2.x, w3.x);
            *(float4*)(dst + 1024) = make_float4(w0.y, w1.y, w2.y, w3.y);
            *(float4*)(dst + 2048) = make_float4(w0.z, w1.z, w2.z, w3.z);
            *(float4*)(dst + 3072) = make_float4(w0.w, w1.w, w2.w, w3.w);
        }
        __syncthreads();

        #pragma unroll 4
        for (int k = 0; k < 32; k++) {
            float4 xa = *(const float4*)(xs + k * 32 + rg * 8);
            float4 xb = *(const float4*)(xs + k * 32 + rg * 8 + 4);
            float xf[8] = {xa.x, xa.y, xa.z, xa.w, xb.x, xb.y, xb.z, xb.w};
            float4 wf[4];
            int sw = (k >> 2) & 7;
            #pragma unroll
            for (int g = 0; g < 4; g++) {
                int co4 = cg + 64 * g;
                wf[g] = *(const float4*)(ws + k * 1024 + ((co4 ^ sw) << 2));
            }
            #pragma unroll
            for (int r = 0; r < 8; r++) {
                #pragma unroll
                for (int g = 0; g < 4; g++) {
                    acc[r][g * 4 + 0] = fmaf(xf[r], wf[g].x, acc[r][g * 4 + 0]);
                    acc[r][g * 4 + 1] = fmaf(xf[r], wf[g].y, acc[r][g * 4 + 1]);
                    acc[r][g * 4 + 2] = fmaf(xf[r], wf[g].z, acc[r][g * 4 + 2]);
                    acc[r][g * 4 + 3] = fmaf(xf[r], wf[g].w, acc[r][g * 4 + 3]);
                }
            }
        }
        __syncthreads();
    }

    // ---------------- Epilogue ----------------
    // zero smem avg buffer (reuse ws[0..1023]); syncs inside row loop order it
    #pragma unroll
    for (int c = tid; c < KDIM; c += NTHREADS) ws[c] = 0.0f;

    float4 bv[4];
    #pragma unroll
    for (int g = 0; g < 4; g++)
        bv[g] = *(const float4*)(bias + cg * 4 + g * 256);

    float pacc[16];
    #pragma unroll
    for (int c = 0; c < 16; c++) pacc[c] = 0.0f;

    const int warp = tid >> 5;
    const int lane = tid & 31;

    for (int r = 0; r < 8; r++) {
        const int grow = rowbase + rg * 8 + r;
        // y = logits + bias + gumbel (in place in acc[r])
        #pragma unroll
        for (int g = 0; g < 4; g++) {
            float4 gv = *(const float4*)(gum + (size_t)grow * KDIM + cg * 4 + g * 256);
            acc[r][g * 4 + 0] += bv[g].x + gv.x;
            acc[r][g * 4 + 1] += bv[g].y + gv.y;
            acc[r][g * 4 + 2] += bv[g].z + gv.z;
            acc[r][g * 4 + 3] += bv[g].w + gv.w;
        }
        // per-thread max/arg (ascending col order -> first-max tie break)
        float vmax = acc[r][0];
        int   varg = cg * 4;
        #pragma unroll
        for (int g = 0; g < 4; g++)
            #pragma unroll
            for (int j = 0; j < 4; j++) {
                int idx = g * 4 + j;
                int col = cg * 4 + g * 256 + j;
                if (acc[r][idx] > vmax) { vmax = acc[r][idx]; varg = col; }
            }
        // warp reduce (prefer larger value; lower index on ties)
        #pragma unroll
        for (int off = 16; off; off >>= 1) {
            float ov = __shfl_down_sync(0xffffffffu, vmax, off);
            int   oa = __shfl_down_sync(0xffffffffu, varg, off);
            if (ov > vmax || (ov == vmax && oa < varg)) { vmax = ov; varg = oa; }
        }
        if (lane == 0) { swmax[warp] = vmax; swarg[warp] = varg; }
        __syncthreads();
        float m0 = swmax[rg * 2], m1 = swmax[rg * 2 + 1];
        int   a0 = swarg[rg * 2], a1 = swarg[rg * 2 + 1];
        float rmax; int rarg;
        if (m0 > m1 || (m0 == m1 && a0 < a1)) { rmax = m0; rarg = a0; }
        else                                  { rmax = m1; rarg = a1; }

        // sum of exp
        float e[16];
        float ps = 0.0f;
        #pragma unroll
        for (int idx = 0; idx < 16; idx++) {
            e[idx] = __expf(acc[r][idx] - rmax);
            ps += e[idx];
        }
        #pragma unroll
        for (int off = 16; off; off >>= 1)
            ps += __shfl_down_sync(0xffffffffu, ps, off);
        if (lane == 0) swsum[warp] = ps;
        __syncthreads();
        float inv = 1.0f / (swsum[rg * 2] + swsum[rg * 2 + 1]);
        #pragma unroll
        for (int idx = 0; idx < 16; idx++) pacc[idx] += e[idx] * inv;

        if (cg == 0) {
            srowarg[rg * 8 + r] = rarg;
            out[(size_t)B * EDIM + grow] = (float)rarg;   // m as float
        }
    }

    __syncthreads();  // srowarg + ws zeroing visible everywhere

    // block-local avg_p reduce, then one global atomic per column
    #pragma unroll
    for (int idx = 0; idx < 16; idx++) {
        int col = cg * 4 + (idx >> 2) * 256 + (idx & 3);
        atomicAdd(ws + col, pacc[idx]);
    }
    __syncthreads();
    for (int c = tid; c < KDIM; c += NTHREADS)
        atomicAdd(&g_avgp[c], ws[c]);

    // z_q = codebook[argmax] gather (coalesced float4)
    #pragma unroll
    for (int q = 0; q < 8; q++) {
        int idx = q * NTHREADS + tid;          // 0..2047
        int row = idx >> 6;                    // 0..31
        int v   = idx & 63;                    // float4 index 0..63
        int arg = srowarg[row];
        float4 cv = *(const float4*)(cb + (size_t)arg * EDIM + v * 4);
        *(float4*)(out + (size_t)(rowbase + row) * EDIM + v * 4) = cv;
    }
}

__global__ void diversity_kernel(float* __restrict__ out, int B) {
    __shared__ float sred[8];
    const int tid = threadIdx.x;
    const float invB = 1.0f / (float)B;
    const float logK = logf((float)KDIM);
    float s = 0.0f;
    for (int c = tid; c < KDIM; c += 256) {
        float p = g_avgp[c] * invB;
        s += p * (logf(fmaxf(p, 1e-9f)) + logK);
    }
    #pragma unroll
    for (int off = 16; off; off >>= 1)
        s += __shfl_down_sync(0xffffffffu, s, off);
    if ((tid & 31) == 0) sred[tid >> 5] = s;
    __syncthreads();
    if (tid == 0) {
        float t = 0.0f;
        #pragma unroll
        for (int w = 0; w < 8; w++) t += sred[w];
        size_t base = (size_t)B * EDIM + B;
        out[base]     = t;     // diversity
        out[base + 1] = 0.0f;  // trailing zeros() scalar
    }
}

extern "C" void kernel_launch(void* const* d_in, const int* in_sizes, int n_in,
                              void* d_out, int out_size) {
    const float* x    = (const float*)d_in[0];   // [B, 1024]
    const float* gum  = (const float*)d_in[1];   // [B, 1024]
    const float* W    = (const float*)d_in[2];   // [1024, 1024]
    const float* bias = (const float*)d_in[3];   // [1024]
    const float* cb   = (const float*)d_in[4];   // [1024, 256]
    float* out = (float*)d_out;

    const int B = in_sizes[0] / NIN;             // 65536
    const int smem_bytes = (32 * 1024 + 32 * 32) * sizeof(float);  // 135168

    cudaFuncSetAttribute(fused_vq_kernel,
                         cudaFuncAttributeMaxDynamicSharedMemorySize, smem_bytes);

    zero_avgp_kernel<<<(KDIM + 255) / 256, 256>>>();
    fused_vq_kernel<<<B / BM, NTHREADS, smem_bytes>>>(x, gum, W, bias, cb, out, B);
    diversity_kernel<<<1, 256>>>(out, B);
}

// round 2
// speedup vs baseline: 8.7638x; 8.7638x over previous
#include <cuda_runtime.h>
#include <math.h>

#define NIN  1024   // n_in
#define KDIM 1024   // K (codebook entries / logit width)
#define EDIM 256    // embedding dim
#define BM   32     // rows per block
#define NTHREADS 256

// cross-block scratch (allowed: __device__ globals). Zero-initialized at load;
// the finisher block restores them to zero every call -> deterministic replays.
__device__ float g_avgp[KDIM];
__device__ unsigned int g_count;

extern __shared__ float smem_dyn[];

// Fused: logits GEMM (fp32) + bias + gumbel + argmax + softmax-sum +
//        avg_p accumulation + codebook gather + m output + diversity finisher.
__global__ __launch_bounds__(NTHREADS, 1)
void fused_vq_kernel(const float* __restrict__ x,      // [B, NIN]
                     const float* __restrict__ gum,    // [B, KDIM]
                     const float* __restrict__ W,      // [KDIM, NIN]
                     const float* __restrict__ bias,   // [KDIM]
                     const float* __restrict__ cb,     // [KDIM, EDIM]
                     float* __restrict__ out,          // z_q | m | div | 0
                     int B)
{
    float* ws = smem_dyn;               // [32 ki][1024 ko], XOR-swizzled quads
    float* xs = smem_dyn + 32 * 1024;   // [32 ki][32 row], XOR-swizzled cols

    __shared__ float swmax[8];
    __shared__ int   swarg[8];
    __shared__ float swsum[8];
    __shared__ int   srowarg[BM];
    __shared__ int   sIsLast;

    const int tid = threadIdx.x;
    const int rg  = tid >> 6;    // 0..3  -> rows rg*8 .. rg*8+7
    const int cg  = tid & 63;    // 0..63 -> cols cg*4 + g*256 + j
    const int rowbase = blockIdx.x * BM;

    float acc[8][16];
    #pragma unroll
    for (int r = 0; r < 8; r++)
        #pragma unroll
        for (int c = 0; c < 16; c++) acc[r][c] = 0.0f;

    const int lrow = tid >> 3;   // 0..31 (x-tile loads)
    const int lkiv = tid & 7;    // 0..7
    const int lb   = tid & 7;    // W-tile: ki quad
    const int lat  = tid >> 3;   // W-tile: base of ko quad

    // ---------------- GEMM main loop ----------------
    for (int kk = 0; kk < NIN; kk += 32) {
        // x tile: [32 rows][32 ki] -> xs[ki][row ^ ((ki>>2)<<2)]
        // (XOR swizzle keeps STS conflict-free; reads stay aligned LDS.128 broadcast)
        {
            float4 xv = *(const float4*)(x + (size_t)(rowbase + lrow) * NIN + kk + lkiv * 4);
            int xc = lrow ^ (lkiv << 2);
            xs[(lkiv * 4 + 0) * 32 + xc] = xv.x;
            xs[(lkiv * 4 + 1) * 32 + xc] = xv.y;
            xs[(lkiv * 4 + 2) * 32 + xc] = xv.z;
            xs[(lkiv * 4 + 3) * 32 + xc] = xv.w;
        }
        // W tile: [1024 ko][32 ki] -> ws[ki][ko] via 4x4 register transpose,
        // stored with quad swizzle (a ^ lb) for conflict-free STS128/LDS128.
        #pragma unroll
        for (int i = 0; i < 8; i++) {
            int a = i * 32 + lat;          // ko quad 0..255
            const float* wp = W + (size_t)(a * 4) * NIN + kk + lb * 4;
            float4 w0 = *(const float4*)(wp);
            float4 w1 = *(const float4*)(wp + NIN);
            float4 w2 = *(const float4*)(wp + 2 * NIN);
            float4 w3 = *(const float4*)(wp + 3 * NIN);
            float* dst = ws + (lb * 4) * 1024 + ((a ^ lb) << 2);
            *(float4*)(dst)        = make_float4(w0.x, w1.x, w2.x, w3.x);
            *(float4*)(dst + 1024) = make_float4(w0.y, w1.y, w2.y, w3.y);
            *(float4*)(dst + 2048) = make_float4(w0.z, w1.z, w2.z, w3.z);
            *(float4*)(dst + 3072) = make_float4(w0.w, w1.w, w2.w, w3.w);
        }
        __syncthreads();

        #pragma unroll 2
        for (int k = 0; k < 32; k++) {
            int xsw = (k >> 2) << 2;                      // x col swizzle (mult of 4)
            float4 xa = *(const float4*)(xs + k * 32 + ((rg * 8) ^ xsw));
            float4 xb = *(const float4*)(xs + k * 32 + ((rg * 8 + 4) ^ xsw));
            float xf[8] = {xa.x, xa.y, xa.z, xa.w, xb.x, xb.y, xb.z, xb.w};
            float4 wf[4];
            int sw = (k >> 2) & 7;
            #pragma unroll
            for (int g = 0; g < 4; g++) {
                int co4 = cg + 64 * g;
                wf[g] = *(const float4*)(ws + k * 1024 + ((co4 ^ sw) << 2));
            }
            #pragma unroll
            for (int r = 0; r < 8; r++) {
                #pragma unroll
                for (int g = 0; g < 4; g++) {
                    acc[r][g * 4 + 0] = fmaf(xf[r], wf[g].x, acc[r][g * 4 + 0]);
                    acc[r][g * 4 + 1] = fmaf(xf[r], wf[g].y, acc[r][g * 4 + 1]);
                    acc[r][g * 4 + 2] = fmaf(xf[r], wf[g].z, acc[r][g * 4 + 2]);
                    acc[r][g * 4 + 3] = fmaf(xf[r], wf[g].w, acc[r][g * 4 + 3]);
                }
            }
        }
        __syncthreads();
    }

    // ---------------- Epilogue ----------------
    // zero smem avg buffer (reuse ws[0..1023]); syncs inside row loop order it
    for (int c = tid; c < KDIM; c += NTHREADS) ws[c] = 0.0f;

    float4 bv[4];
    #pragma unroll
    for (int g = 0; g < 4; g++)
        bv[g] = *(const float4*)(bias + cg * 4 + g * 256);

    float pacc[16];
    #pragma unroll
    for (int c = 0; c < 16; c++) pacc[c] = 0.0f;

    const int warp = tid >> 5;
    const int lane = tid & 31;

    #pragma unroll
    for (int r = 0; r < 8; r++) {
        const int grow = rowbase + rg * 8 + r;
        // y = logits + bias + gumbel (in place in acc[r])
        #pragma unroll
        for (int g = 0; g < 4; g++) {
            float4 gv = *(const float4*)(gum + (size_t)grow * KDIM + cg * 4 + g * 256);
            acc[r][g * 4 + 0] += bv[g].x + gv.x;
            acc[r][g * 4 + 1] += bv[g].y + gv.y;
            acc[r][g * 4 + 2] += bv[g].z + gv.z;
            acc[r][g * 4 + 3] += bv[g].w + gv.w;
        }
        // per-thread max/arg (ascending col order -> first-max tie break)
        float vmax = acc[r][0];
        int   varg = cg * 4;
        #pragma unroll
        for (int g = 0; g < 4; g++)
            #pragma unroll
            for (int j = 0; j < 4; j++) {
                int idx = g * 4 + j;
                int col = cg * 4 + g * 256 + j;
                if (acc[r][idx] > vmax) { vmax = acc[r][idx]; varg = col; }
            }
        // warp reduce (prefer larger value; lower index on ties)
        #pragma unroll
        for (int off = 16; off; off >>= 1) {
            float ov = __shfl_down_sync(0xffffffffu, vmax, off);
            int   oa = __shfl_down_sync(0xffffffffu, varg, off);
            if (ov > vmax || (ov == vmax && oa < varg)) { vmax = ov; varg = oa; }
        }
        if (lane == 0) { swmax[warp] = vmax; swarg[warp] = varg; }
        __syncthreads();
        float m0 = swmax[rg * 2], m1 = swmax[rg * 2 + 1];
        int   a0 = swarg[rg * 2], a1 = swarg[rg * 2 + 1];
        float rmax; int rarg;
        if (m0 > m1 || (m0 == m1 && a0 < a1)) { rmax = m0; rarg = a0; }
        else                                  { rmax = m1; rarg = a1; }

        // exp in place + sum
        float ps = 0.0f;
        #pragma unroll
        for (int idx = 0; idx < 16; idx++) {
            acc[r][idx] = __expf(acc[r][idx] - rmax);
            ps += acc[r][idx];
        }
        #pragma unroll
        for (int off = 16; off; off >>= 1)
            ps += __shfl_down_sync(0xffffffffu, ps, off);
        if (lane == 0) swsum[warp] = ps;
        __syncthreads();
        float inv = 1.0f / (swsum[rg * 2] + swsum[rg * 2 + 1]);
        #pragma unroll
        for (int idx = 0; idx < 16; idx++) pacc[idx] += acc[r][idx] * inv;

        if (cg == 0) {
            srowarg[rg * 8 + r] = rarg;
            out[(size_t)B * EDIM + grow] = (float)rarg;   // m as float
        }
    }

    __syncthreads();  // srowarg + ws zeroing visible everywhere

    // block-local avg_p reduce, then one global atomic per column
    #pragma unroll
    for (int idx = 0; idx < 16; idx++) {
        int col = cg * 4 + (idx >> 2) * 256 + (idx & 3);
        atomicAdd(ws + col, pacc[idx]);
    }
    __syncthreads();
    for (int c = tid; c < KDIM; c += NTHREADS)
        atomicAdd(&g_avgp[c], ws[c]);

    // z_q = codebook[argmax] gather (coalesced float4)
    #pragma unroll
    for (int q = 0; q < 8; q++) {
        int idx = q * NTHREADS + tid;          // 0..2047
        int row = idx >> 6;                    // 0..31
        int v   = idx & 63;                    // float4 index 0..63
        int arg = srowarg[row];
        float4 cv = *(const float4*)(cb + (size_t)arg * EDIM + v * 4);
        *(float4*)(out + (size_t)(rowbase + row) * EDIM + v * 4) = cv;
    }

    // ---------------- Diversity finisher (last block) ----------------
    __threadfence();
    if (tid == 0) {
        unsigned int old = atomicAdd(&g_count, 1u);
        sIsLast = (old == gridDim.x - 1) ? 1 : 0;
    }
    __syncthreads();
    if (sIsLast) {
        const float invB = 1.0f / (float)B;
        const float logK = logf((float)KDIM);
        float s = 0.0f;
        for (int c = tid; c < KDIM; c += NTHREADS) {
            float p = g_avgp[c] * invB;
            s += p * (logf(fmaxf(p, 1e-9f)) + logK);
            g_avgp[c] = 0.0f;                      // restore scratch for next call
        }
        #pragma unroll
        for (int off = 16; off; off >>= 1)
            s += __shfl_down_sync(0xffffffffu, s, off);
        if (lane == 0) swsum[warp] = s;            // reuse swsum (safe: after all uses)
        __syncthreads();
        if (tid == 0) {
            float t = 0.0f;
            #pragma unroll
            for (int w = 0; w < 8; w++) t += swsum[w];
            size_t base = (size_t)B * EDIM + B;
            out[base]     = t;     // diversity
            out[base + 1] = 0.0f;  // trailing zeros() scalar
            g_count = 0u;          // restore counter for next call
        }
    }
}

extern "C" void kernel_launch(void* const* d_in, const int* in_sizes, int n_in,
                              void* d_out, int out_size) {
    const float* x    = (const float*)d_in[0];   // [B, 1024]
    const float* gum  = (const float*)d_in[1];   // [B, 1024]
    const float* W    = (const float*)d_in[2];   // [1024, 1024]
    const float* bias = (const float*)d_in[3];   // [1024]
    const float* cb   = (const float*)d_in[4];   // [1024, 256]
    float* out = (float*)d_out;

    const int B = in_sizes[0] / NIN;             // 65536
    const int smem_bytes = (32 * 1024 + 32 * 32) * sizeof(float);  // 135168

    cudaFuncSetAttribute(fused_vq_kernel,
                         cudaFuncAttributeMaxDynamicSharedMemorySize, smem_bytes);

    fused_vq_kernel<<<B / BM, NTHREADS, smem_bytes>>>(x, gum, W, bias, cb, out, B);
}

// round 4
// speedup vs baseline: 14.0954x; 1.6084x over previous
#include <cuda_runtime.h>
#include <math.h>
#include <stdint.h>

#define NIN   1024
#define KDIM  1024
#define EDIM  256
#define BM    32
#define KSTEP 16
#define NKIT  (NIN / KSTEP)          // 64
#define ROWF  20                      // padded floats per smem/gmem slab row
#define XSLAB (BM * ROWF * 4)         // 2560 B
#define WSLAB (KDIM * ROWF * 4)       // 81920 B
#define STAGE (XSLAB + WSLAB)         // 84480 B
#define SMEM_DYN (2 * STAGE)          // 168960 B
#define YSTR  1032                    // epilogue y smem row stride (floats)

// ---------------- device scratch (__device__ globals allowed) ----------------
__device__ __align__(128) float g_xt[(size_t)2048 * 64 * (XSLAB / 4)];  // 335 MB
__device__ __align__(128) float g_wt[(size_t)64 * (WSLAB / 4)];         // 5.2 MB
__device__ float g_avgp[KDIM];
__device__ unsigned int g_count;

// ---------------- PTX helpers ----------------
__device__ __forceinline__ uint32_t smem_u32(const void* p) {
    uint32_t a;
    asm("{ .reg .u64 t; cvta.to.shared.u64 t, %1; cvt.u32.u64 %0, t; }" : "=r"(a) : "l"(p));
    return a;
}
__device__ __forceinline__ uint32_t cluster_rank() {
    uint32_t r; asm("mov.u32 %0, %%cluster_ctarank;" : "=r"(r)); return r;
}
#define MBAR_INIT(a, n) \
    asm volatile("mbarrier.init.shared.b64 [%0], %1;" :: "r"(a), "r"((uint32_t)(n)) : "memory")
#define MBAR_EXPECT_TX(a, b) \
    asm volatile("mbarrier.arrive.expect_tx.shared.b64 _, [%0], %1;" :: "r"(a), "r"((uint32_t)(b)) : "memory")
#define MBAR_ARRIVE_RANK(a, rk) \
    asm volatile("{ .reg .b32 ra; mapa.shared::cluster.u32 ra, %0, %1; " \
                 "mbarrier.arrive.shared::cluster.b64 _, [ra]; }" :: "r"(a), "r"(rk) : "memory")
#define MBAR_WAIT(a, p) do { \
    uint32_t _m = (a); uint32_t _p = (p); uint32_t _d; \
    asm volatile("{\n\t.reg .pred q;\n\tmbarrier.try_wait.parity.acquire.cta.shared::cta.b64 q, [%1], %2;\n\tselp.b32 %0,1,0,q;\n\t}" \
        : "=r"(_d) : "r"(_m), "r"(_p) : "memory"); \
    if (!_d) { \
        asm volatile("{\n\t.reg .pred Q;\n\tWL_%=:\n\tmbarrier.try_wait.parity.acquire.cta.shared::cta.b64 Q, [%0], %1, 0x989680;\n\t@Q bra.uni WD_%=;\n\tbra.uni WL_%=;\n\tWD_%=:\n\t}" \
            :: "r"(_m), "r"(_p) : "memory"); \
    } } while (0)
#define CLUSTER_SYNC() do { \
    asm volatile("barrier.cluster.arrive.aligned;" ::: "memory"); \
    asm volatile("barrier.cluster.wait.aligned;" ::: "memory"); } while (0)

__device__ __forceinline__ void bulk_g2s(uint32_t dst, const void* src, uint32_t bytes, uint32_t mbar) {
    asm volatile("cp.async.bulk.shared::cluster.global.mbarrier::complete_tx::bytes [%0], [%1], %2, [%3];"
        :: "r"(dst), "l"(src), "r"(bytes), "r"(mbar) : "memory");
}
__device__ __forceinline__ void bulk_g2s_mc(uint32_t dst, const void* src, uint32_t bytes, uint32_t mbar, uint16_t mask) {
    asm volatile("cp.async.bulk.shared::cluster.global.mbarrier::complete_tx::bytes.multicast::cluster [%0], [%1], %2, [%3], %4;"
        :: "r"(dst), "l"(src), "r"(bytes), "r"(mbar), "h"(mask) : "memory");
}

__device__ __forceinline__ uint32_t f2tf32(float f) {
    uint32_t r; asm("cvt.rna.tf32.f32 %0, %1;" : "=r"(r) : "f"(f)); return r;
}
__device__ __forceinline__ void mma_tf32(float d[4], uint32_t a0, uint32_t a1, uint32_t a2, uint32_t a3,
                                         uint32_t b0, uint32_t b1) {
    asm volatile(
        "mma.sync.aligned.m16n8k8.row.col.f32.tf32.tf32.f32 "
        "{%0,%1,%2,%3}, {%4,%5,%6,%7}, {%8,%9}, {%0,%1,%2,%3};"
        : "+f"(d[0]), "+f"(d[1]), "+f"(d[2]), "+f"(d[3])
        : "r"(a0), "r"(a1), "r"(a2), "r"(a3), "r"(b0), "r"(b1));
}

// ---------------- rearrange kernels: padded contiguous slabs for bulk copy ----------------
// g_xt[rowtile][kchunk][32 rows][20 floats]  (floats 16..19 zero pad)
__global__ __launch_bounds__(256) void rearr_x_kernel(const float* __restrict__ x) {
    extern __shared__ float sx[];                 // [32][1032]
    const int tid = threadIdx.x;
    const int rt  = blockIdx.x;
    for (int o = tid; o < 32 * 256; o += 256) {   // coalesced load 32x1024
        int r = o >> 8, c4 = o & 255;
        float4 v = ((const float4*)x)[(size_t)(rt * 32 + r) * 256 + c4];
        *(float4*)&sx[r * YSTR + c4 * 4] = v;
    }
    __syncthreads();
    float4* dst = (float4*)(g_xt + (size_t)rt * 64 * (XSLAB / 4));
    for (int o = tid; o < 64 * 32 * 5; o += 256) {
        int c = o / 160, rem = o % 160, r = rem / 5, q = rem % 5;
        float4 v = (q < 4) ? *(float4*)&sx[r * YSTR + c * 16 + q * 4]
                           : make_float4(0.f, 0.f, 0.f, 0.f);
        dst[o] = v;
    }
}
// g_wt[kchunk][1024 ko][20 floats]
__global__ __launch_bounds__(256) void rearr_w_kernel(const float* __restrict__ W) {
    const int tid = threadIdx.x;
    const int c = blockIdx.x;
    float4* dst = (float4*)(g_wt + (size_t)c * (WSLAB / 4));
    for (int o = tid; o < 1024 * 5; o += 256) {
        int ko = o / 5, q = o % 5;
        float4 v = (q < 4) ? *(const float4*)(W + (size_t)ko * NIN + c * 16 + q * 4)
                           : make_float4(0.f, 0.f, 0.f, 0.f);
        dst[o] = v;
    }
}

// ---------------- fused GEMM (3xTF32 mma.sync) + softmax epilogue ----------------
__global__ __launch_bounds__(256, 1) __cluster_dims__(2, 1, 1)
void fused_vq_kernel(const float* __restrict__ gum, const float* __restrict__ bias,
                     const float* __restrict__ cb, float* __restrict__ out, int B)
{
    extern __shared__ __align__(128) unsigned char smem[];
    __shared__ __align__(8) unsigned long long mb_full[2], mb_empty[2];
    __shared__ float savgp[KDIM];
    __shared__ float sred[8];
    __shared__ int sIsLast;

    const int tid  = threadIdx.x;
    const int wid  = tid >> 5;
    const int lane = tid & 31;
    const int r0   = lane >> 2;        // fragment group id (0..7)
    const int q    = lane & 3;         // fragment thread-in-group
    const uint32_t rank = cluster_rank();
    const int rowbase = blockIdx.x * BM;
    const int wbase   = wid * 128;

    const uint32_t smem_b = smem_u32(smem);
    uint32_t full_a[2]  = { smem_u32(&mb_full[0]),  smem_u32(&mb_full[1]) };
    uint32_t empty_a[2] = { smem_u32(&mb_empty[0]), smem_u32(&mb_empty[1]) };

    if (tid == 0) {
        MBAR_INIT(full_a[0], 1);  MBAR_INIT(full_a[1], 1);
        MBAR_INIT(empty_a[0], 2); MBAR_INIT(empty_a[1], 2);   // one consumer arrival per CTA
    }
    __syncthreads();
    CLUSTER_SYNC();   // peer barriers valid before any multicast

    // prologue fills: stages 0, 1
    if (tid == 0) {
        #pragma unroll
        for (int i = 0; i < 2; i++) {
            MBAR_EXPECT_TX(full_a[i], STAGE);
            bulk_g2s(smem_b + i * STAGE,
                     g_xt + ((size_t)blockIdx.x * 64 + i) * (XSLAB / 4), XSLAB, full_a[i]);
            bulk_g2s_mc(smem_b + i * STAGE + XSLAB + rank * (WSLAB / 2),
                        (const unsigned char*)g_wt + (size_t)i * WSLAB + rank * (WSLAB / 2),
                        WSLAB / 2, full_a[i], (uint16_t)0x3);
        }
    }

    float d[2][16][4];
    #pragma unroll
    for (int m = 0; m < 2; m++)
        #pragma unroll
        for (int j = 0; j < 16; j++)
            #pragma unroll
            for (int t = 0; t < 4; t++) d[m][j][t] = 0.0f;

    for (int i = 0; i < NKIT; i++) {
        const int s = i & 1;
        MBAR_WAIT(full_a[s], (i >> 1) & 1);
        const float* xs = (const float*)(smem + s * STAGE);
        const float* ws = (const float*)(smem + s * STAGE + XSLAB);

        #pragma unroll
        for (int k8 = 0; k8 < 2; k8++) {
            const int kb = k8 * 8;
            uint32_t ah[8], al[8];
            #pragma unroll
            for (int mt = 0; mt < 2; mt++)
                #pragma unroll
                for (int kk = 0; kk < 2; kk++)
                    #pragma unroll
                    for (int h = 0; h < 2; h++) {
                        float v = xs[(mt * 16 + h * 8 + r0) * ROWF + kb + q + kk * 4];
                        uint32_t hi = f2tf32(v);
                        int idx = mt * 4 + kk * 2 + h;
                        ah[idx] = hi;
                        al[idx] = f2tf32(v - __uint_as_float(hi));
                    }
            #pragma unroll
            for (int j = 0; j < 16; j++) {
                float b0f = ws[(wbase + j * 8 + r0) * ROWF + kb + q];
                float b1f = ws[(wbase + j * 8 + r0) * ROWF + kb + q + 4];
                uint32_t bh0 = f2tf32(b0f), bh1 = f2tf32(b1f);
                uint32_t bl0 = f2tf32(b0f - __uint_as_float(bh0));
                uint32_t bl1 = f2tf32(b1f - __uint_as_float(bh1));
                #pragma unroll
                for (int mt = 0; mt < 2; mt++) {
                    mma_tf32(d[mt][j], ah[mt*4+0], ah[mt*4+1], ah[mt*4+2], ah[mt*4+3], bh0, bh1);
                    mma_tf32(d[mt][j], ah[mt*4+0], ah[mt*4+1], ah[mt*4+2], ah[mt*4+3], bl0, bl1);
                    mma_tf32(d[mt][j], al[mt*4+0], al[mt*4+1], al[mt*4+2], al[mt*4+3], bh0, bh1);
                }
            }
        }
        __syncthreads();                       // all LDS on stage s done
        if (tid == 0) {
            MBAR_ARRIVE_RANK(empty_a[s], 0);   // signal both CTAs' empty barriers
            MBAR_ARRIVE_RANK(empty_a[s], 1);
            if (i + 2 < NKIT) {
                MBAR_WAIT(empty_a[s], (i >> 1) & 1);   // both consumers done with s
                MBAR_EXPECT_TX(full_a[s], STAGE);
                bulk_g2s(smem_b + s * STAGE,
                         g_xt + ((size_t)blockIdx.x * 64 + (i + 2)) * (XSLAB / 4), XSLAB, full_a[s]);
                bulk_g2s_mc(smem_b + s * STAGE + XSLAB + rank * (WSLAB / 2),
                            (const unsigned char*)g_wt + (size_t)(i + 2) * WSLAB + rank * (WSLAB / 2),
                            WSLAB / 2, full_a[s], (uint16_t)0x3);
            }
        }
    }

    // ---------------- epilogue: acc -> smem y, then softmax/argmax/avg_p ----------------
    __syncthreads();
    float* y = (float*)smem;                   // [32][YSTR]
    #pragma unroll
    for (int mt = 0; mt < 2; mt++)
        #pragma unroll
        for (int j = 0; j < 16; j++) {
            int row = mt * 16 + r0;
            int col = wbase + j * 8 + 2 * q;
            *(float2*)&y[row * YSTR + col]       = make_float2(d[mt][j][0], d[mt][j][1]);
            *(float2*)&y[(row + 8) * YSTR + col] = make_float2(d[mt][j][2], d[mt][j][3]);
        }
    for (int c = tid; c < KDIM; c += 256) savgp[c] = 0.0f;
    __syncthreads();

    float pacc[32];
    #pragma unroll
    for (int t = 0; t < 32; t++) pacc[t] = 0.0f;

    for (int rr = 0; rr < 4; rr++) {
        const int lrow = wid + rr * 8;
        const int grow = rowbase + lrow;
        float v[32];
        #pragma unroll
        for (int g = 0; g < 8; g++) {
            float4 t  = *(float4*)&y[lrow * YSTR + g * 128 + lane * 4];
            float4 bv = *(const float4*)(bias + g * 128 + lane * 4);
            float4 gv = *(const float4*)(gum + (size_t)grow * KDIM + g * 128 + lane * 4);
            v[g*4+0] = t.x + bv.x + gv.x;  v[g*4+1] = t.y + bv.y + gv.y;
            v[g*4+2] = t.z + bv.z + gv.z;  v[g*4+3] = t.w + bv.w + gv.w;
        }
        float vm = v[0]; int va = lane * 4;
        #pragma unroll
        for (int g = 0; g < 8; g++)
            #pragma unroll
            for (int j = 0; j < 4; j++) {
                int col = g * 128 + lane * 4 + j;
                if (v[g*4+j] > vm) { vm = v[g*4+j]; va = col; }
            }
        #pragma unroll
        for (int off = 16; off; off >>= 1) {
            float ov = __shfl_xor_sync(0xffffffffu, vm, off);
            int   oa = __shfl_xor_sync(0xffffffffu, va, off);
            if (ov > vm || (ov == vm && oa < va)) { vm = ov; va = oa; }
        }
        float sum = 0.0f;
        #pragma unroll
        for (int t = 0; t < 32; t++) { v[t] = __expf(v[t] - vm); sum += v[t]; }
        #pragma unroll
        for (int off = 16; off; off >>= 1)
            sum += __shfl_xor_sync(0xffffffffu, sum, off);
        float inv = 1.0f / sum;
        #pragma unroll
        for (int t = 0; t < 32; t++) pacc[t] += v[t] * inv;

        if (lane == 0) out[(size_t)B * EDIM + grow] = (float)va;   // m
        const float4* cbr = (const float4*)(cb + (size_t)va * EDIM);
        float4* zo = (float4*)(out + (size_t)grow * EDIM);
        zo[lane]      = cbr[lane];
        zo[lane + 32] = cbr[lane + 32];
    }

    #pragma unroll
    for (int t = 0; t < 32; t++) {
        int col = (t >> 2) * 128 + lane * 4 + (t & 3);
        atomicAdd(&savgp[col], pacc[t]);
    }
    __syncthreads();
    for (int c = tid; c < KDIM; c += 256)
        atomicAdd(&g_avgp[c], savgp[c]);

    // diversity finisher (last block) + scratch restore
    __threadfence();
    if (tid == 0) {
        unsigned int old = atomicAdd(&g_count, 1u);
        sIsLast = (old == gridDim.x - 1) ? 1 : 0;
    }
    __syncthreads();
    if (sIsLast) {
        const float invB = 1.0f / (float)B;
        const float logK = logf((float)KDIM);
        float sdiv = 0.0f;
        for (int c = tid; c < KDIM; c += 256) {
            float p = g_avgp[c] * invB;
            sdiv += p * (logf(fmaxf(p, 1e-9f)) + logK);
            g_avgp[c] = 0.0f;
        }
        #pragma unroll
        for (int off = 16; off; off >>= 1)
            sdiv += __shfl_xor_sync(0xffffffffu, sdiv, off);
        if (lane == 0) sred[wid] = sdiv;
        __syncthreads();
        if (tid == 0) {
            float t = 0.0f;
            #pragma unroll
            for (int w = 0; w < 8; w++) t += sred[w];
            size_t base = (size_t)B * EDIM + B;
            out[base]     = t;
            out[base + 1] = 0.0f;
            g_count = 0u;
        }
    }

    CLUSTER_SYNC();   // no CTA exits while peer multicast may target its smem
}

// ---------------- launch ----------------
extern "C" void kernel_launch(void* const* d_in, const int* in_sizes, int n_in,
                              void* d_out, int out_size) {
    const float* x    = (const float*)d_in[0];
    const float* gum  = (const float*)d_in[1];
    const float* W    = (const float*)d_in[2];
    const float* bias = (const float*)d_in[3];
    const float* cb   = (const float*)d_in[4];
    float* out = (float*)d_out;

    const int B = in_sizes[0] / NIN;             // 65536

    cudaFuncSetAttribute(rearr_x_kernel, cudaFuncAttributeMaxDynamicSharedMemorySize, 32 * YSTR * 4);
    cudaFuncSetAttribute(fused_vq_kernel, cudaFuncAttributeMaxDynamicSharedMemorySize, SMEM_DYN);

    rearr_x_kernel<<<B / BM, 256, 32 * YSTR * 4>>>(x);
    rearr_w_kernel<<<NKIT, 256>>>(W);
    fused_vq_kernel<<<B / BM, 256, SMEM_DYN>>>(gum, bias, cb, out, B);
}

// round 5
// speedup vs baseline: 34.7659x; 2.4665x over previous
#include <cuda_runtime.h>
#include <cuda_bf16.h>
#include <math.h>
#include <stdint.h>

#define NIN   1024
#define KDIM  1024
#define EDIM  256
#define BM    32
#define NKIT  64                       // K/16
#define ASLAB 1024                     // 32 rows x 32B bf16 per kchunk
#define WSLAB 32768                    // 1024 ko x 32B bf16 per kchunk
#define STAGE (ASLAB + WSLAB)          // 33792
#define NSTAGE 4
#define SMEM_DYN (NSTAGE * STAGE)      // 135168
#define YSTR  1032
#define MARGIN 0.08f

// ---------------- device scratch ----------------
__device__ __align__(128) unsigned char g_xs[(size_t)2048 * 64 * ASLAB];  // 134MB bf16 x-slabs
__device__ __align__(128) unsigned char g_ws[(size_t)64 * WSLAB];         // 2MB bf16 w-slab
__device__ float g_avgp[KDIM];
__device__ unsigned int g_count;
__device__ int g_nambig;
__device__ int g_amb[65536][32];       // [0]=row [1]=n [2..31]=cols

// ---------------- PTX helpers ----------------
__device__ __forceinline__ uint32_t smem_u32(const void* p) {
    uint32_t a;
    asm("{ .reg .u64 t; cvta.to.shared.u64 t, %1; cvt.u32.u64 %0, t; }" : "=r"(a) : "l"(p));
    return a;
}
__device__ __forceinline__ uint32_t cluster_rank() {
    uint32_t r; asm("mov.u32 %0, %%cluster_ctarank;" : "=r"(r)); return r;
}
#define MBAR_INIT(a, n) \
    asm volatile("mbarrier.init.shared.b64 [%0], %1;" :: "r"(a), "r"((uint32_t)(n)) : "memory")
#define MBAR_EXPECT_TX(a, b) \
    asm volatile("mbarrier.arrive.expect_tx.shared.b64 _, [%0], %1;" :: "r"(a), "r"((uint32_t)(b)) : "memory")
#define MBAR_ARRIVE_RANK(a, rk) \
    asm volatile("{ .reg .b32 ra; mapa.shared::cluster.u32 ra, %0, %1; " \
                 "mbarrier.arrive.shared::cluster.b64 _, [ra]; }" :: "r"(a), "r"(rk) : "memory")
#define MBAR_WAIT(a, p) do { \
    uint32_t _m = (a); uint32_t _p = (p); uint32_t _d; \
    asm volatile("{\n\t.reg .pred q;\n\tmbarrier.try_wait.parity.acquire.cta.shared::cta.b64 q, [%1], %2;\n\tselp.b32 %0,1,0,q;\n\t}" \
        : "=r"(_d) : "r"(_m), "r"(_p) : "memory"); \
    if (!_d) { \
        asm volatile("{\n\t.reg .pred Q;\n\tWL_%=:\n\tmbarrier.try_wait.parity.acquire.cta.shared::cta.b64 Q, [%0], %1, 0x989680;\n\t@Q bra.uni WD_%=;\n\tbra.uni WL_%=;\n\tWD_%=:\n\t}" \
            :: "r"(_m), "r"(_p) : "memory"); \
    } } while (0)
#define CLUSTER_SYNC() do { \
    asm volatile("barrier.cluster.arrive.aligned;" ::: "memory"); \
    asm volatile("barrier.cluster.wait.aligned;" ::: "memory"); } while (0)

__device__ __forceinline__ void bulk_g2s(uint32_t dst, const void* src, uint32_t bytes, uint32_t mbar) {
    asm volatile("cp.async.bulk.shared::cluster.global.mbarrier::complete_tx::bytes [%0], [%1], %2, [%3];"
        :: "r"(dst), "l"(src), "r"(bytes), "r"(mbar) : "memory");
}
__device__ __forceinline__ void bulk_g2s_mc(uint32_t dst, const void* src, uint32_t bytes, uint32_t mbar, uint16_t mask) {
    asm volatile("cp.async.bulk.shared::cluster.global.mbarrier::complete_tx::bytes.multicast::cluster [%0], [%1], %2, [%3], %4;"
        :: "r"(dst), "l"(src), "r"(bytes), "r"(mbar), "h"(mask) : "memory");
}

__device__ __forceinline__ void mma_bf16(float d[4], uint32_t a0, uint32_t a1, uint32_t a2, uint32_t a3,
                                         uint32_t b0, uint32_t b1) {
    asm volatile(
        "mma.sync.aligned.m16n8k16.row.col.f32.bf16.bf16.f32 "
        "{%0,%1,%2,%3}, {%4,%5,%6,%7}, {%8,%9}, {%0,%1,%2,%3};"
        : "+f"(d[0]), "+f"(d[1]), "+f"(d[2]), "+f"(d[3])
        : "r"(a0), "r"(a1), "r"(a2), "r"(a3), "r"(b0), "r"(b1));
}

// chunk permutation: slot p holds k-pair c where p = (c&3)*2 + (c>>2)
__device__ __forceinline__ int kperm(int c) { return (c & 3) * 2 + (c >> 2); }
__device__ __forceinline__ uint32_t packbf2(float lo, float hi) {
    __nv_bfloat162 h = __floats2bfloat162_rn(lo, hi);
    return *(uint32_t*)&h;
}

// ---------------- rearrange: bf16 k-permuted slabs ----------------
// g_xs: [rowtile 2048][kchunk 64][row 32][8 b32 slots]
__global__ __launch_bounds__(256) void rearr_x_kernel(const float* __restrict__ x) {
    const int tid = threadIdx.x;
    const int rt  = blockIdx.x;
    uint32_t* dst = (uint32_t*)(g_xs + (size_t)rt * 64 * ASLAB);
    for (int it = 0; it < 32; it++) {
        int kchunk = it * 2 + (tid >> 7);
        int r      = (tid >> 2) & 31;
        int c4     = tid & 3;
        float4 v = *(const float4*)(x + (size_t)(rt * 32 + r) * NIN + kchunk * 16 + c4 * 4);
        uint32_t* row = dst + (kchunk * 32 + r) * 8;
        row[kperm(2 * c4)]     = packbf2(v.x, v.y);
        row[kperm(2 * c4 + 1)] = packbf2(v.z, v.w);
    }
}
// g_ws: [kchunk 64][ko 1024][8 b32 slots]
__global__ __launch_bounds__(256) void rearr_w_kernel(const float* __restrict__ W) {
    const int tid = threadIdx.x;
    const int kchunk = blockIdx.x;
    if (kchunk == 0 && tid == 0) g_nambig = 0;          // reset worklist counter
    uint32_t* dst = (uint32_t*)(g_ws + (size_t)kchunk * WSLAB);
    for (int it = 0; it < 16; it++) {
        int o  = it * 256 + tid;
        int ko = o >> 2;
        int c4 = o & 3;
        float4 v = *(const float4*)(W + (size_t)ko * NIN + kchunk * 16 + c4 * 4);
        uint32_t* row = dst + ko * 8;
        row[kperm(2 * c4)]     = packbf2(v.x, v.y);
        row[kperm(2 * c4 + 1)] = packbf2(v.z, v.w);
    }
}

// ---------------- fused bf16 GEMM + softmax/argmax/avg_p epilogue ----------------
__global__ __launch_bounds__(256, 1) __cluster_dims__(2, 1, 1)
void fused_vq_kernel(const float* __restrict__ gum, const float* __restrict__ bias,
                     const float* __restrict__ cb, float* __restrict__ out, int B)
{
    extern __shared__ __align__(128) unsigned char smem[];
    __shared__ __align__(8) unsigned long long mb_full[NSTAGE], mb_empty[NSTAGE];
    __shared__ float savgp[KDIM];
    __shared__ float sred[8];
    __shared__ int scnt[8];
    __shared__ int scols[8][30];
    __shared__ int sIsLast;

    const int tid  = threadIdx.x;
    const int wid  = tid >> 5;
    const int lane = tid & 31;
    const int r0   = lane >> 2;
    const int q    = lane & 3;
    const uint32_t rank = cluster_rank();
    const int rowbase = blockIdx.x * BM;
    const int wbase   = wid * 128;

    const uint32_t smem_b = smem_u32(smem);
    uint32_t full_a[NSTAGE], empty_a[NSTAGE];
    #pragma unroll
    for (int s = 0; s < NSTAGE; s++) {
        full_a[s]  = smem_u32(&mb_full[s]);
        empty_a[s] = smem_u32(&mb_empty[s]);
    }

    if (tid == 0) {
        #pragma unroll
        for (int s = 0; s < NSTAGE; s++) { MBAR_INIT(full_a[s], 1); MBAR_INIT(empty_a[s], 2); }
    }
    __syncthreads();
    CLUSTER_SYNC();

    const unsigned char* asrc = g_xs + (size_t)blockIdx.x * 64 * ASLAB;
    const unsigned char* wsrc = g_ws + rank * (WSLAB / 2);

    if (tid == 0) {
        #pragma unroll
        for (int i = 0; i < NSTAGE; i++) {
            MBAR_EXPECT_TX(full_a[i], STAGE);
            bulk_g2s(smem_b + i * STAGE, asrc + (size_t)i * ASLAB, ASLAB, full_a[i]);
            bulk_g2s_mc(smem_b + i * STAGE + ASLAB + rank * (WSLAB / 2),
                        wsrc + (size_t)i * WSLAB, WSLAB / 2, full_a[i], (uint16_t)0x3);
        }
    }

    float d[2][16][4];
    #pragma unroll
    for (int m = 0; m < 2; m++)
        #pragma unroll
        for (int j = 0; j < 16; j++)
            #pragma unroll
            for (int t = 0; t < 4; t++) d[m][j][t] = 0.0f;

    for (int i = 0; i < NKIT; i++) {
        const int s = i & (NSTAGE - 1);
        MBAR_WAIT(full_a[s], (i >> 2) & 1);
        const uint32_t* As = (const uint32_t*)(smem + s * STAGE);
        const uint32_t* Ws = (const uint32_t*)(smem + s * STAGE + ASLAB);

        uint2 a[2][2];
        #pragma unroll
        for (int mt = 0; mt < 2; mt++) {
            a[mt][0] = *(const uint2*)&As[(mt * 16 + r0) * 8 + 2 * q];       // a0, a2
            a[mt][1] = *(const uint2*)&As[(mt * 16 + r0 + 8) * 8 + 2 * q];   // a1, a3
        }
        #pragma unroll
        for (int j = 0; j < 16; j++) {
            uint2 b = *(const uint2*)&Ws[(wbase + j * 8 + r0) * 8 + 2 * q];
            mma_bf16(d[0][j], a[0][0].x, a[0][1].x, a[0][0].y, a[0][1].y, b.x, b.y);
            mma_bf16(d[1][j], a[1][0].x, a[1][1].x, a[1][0].y, a[1][1].y, b.x, b.y);
        }
        __syncthreads();
        if (tid == 0) {
            MBAR_ARRIVE_RANK(empty_a[s], 0);
            MBAR_ARRIVE_RANK(empty_a[s], 1);
            if (i + NSTAGE < NKIT) {
                MBAR_WAIT(empty_a[s], (i >> 2) & 1);
                MBAR_EXPECT_TX(full_a[s], STAGE);
                bulk_g2s(smem_b + s * STAGE, asrc + (size_t)(i + NSTAGE) * ASLAB, ASLAB, full_a[s]);
                bulk_g2s_mc(smem_b + s * STAGE + ASLAB + rank * (WSLAB / 2),
                            wsrc + (size_t)(i + NSTAGE) * WSLAB, WSLAB / 2, full_a[s], (uint16_t)0x3);
            }
        }
    }

    // ---------------- epilogue ----------------
    __syncthreads();
    float* y = (float*)smem;                   // [32][YSTR]
    #pragma unroll
    for (int mt = 0; mt < 2; mt++)
        #pragma unroll
        for (int j = 0; j < 16; j++) {
            int row = mt * 16 + r0;
            int col = wbase + j * 8 + 2 * q;
            *(float2*)&y[row * YSTR + col]       = make_float2(d[mt][j][0], d[mt][j][1]);
            *(float2*)&y[(row + 8) * YSTR + col] = make_float2(d[mt][j][2], d[mt][j][3]);
        }
    for (int c = tid; c < KDIM; c += 256) savgp[c] = 0.0f;
    __syncthreads();

    float pacc[32];
    #pragma unroll
    for (int t = 0; t < 32; t++) pacc[t] = 0.0f;

    for (int rr = 0; rr < 4; rr++) {
        const int lrow = wid + rr * 8;
        const int grow = rowbase + lrow;
        float v[32];
        #pragma unroll
        for (int g = 0; g < 8; g++) {
            float4 t  = *(float4*)&y[lrow * YSTR + g * 128 + lane * 4];
            float4 bv = *(const float4*)(bias + g * 128 + lane * 4);
            float4 gv = *(const float4*)(gum + (size_t)grow * KDIM + g * 128 + lane * 4);
            v[g*4+0] = t.x + bv.x + gv.x;  v[g*4+1] = t.y + bv.y + gv.y;
            v[g*4+2] = t.z + bv.z + gv.z;  v[g*4+3] = t.w + bv.w + gv.w;
        }
        float vm = v[0]; int va = lane * 4;
        #pragma unroll
        for (int g = 0; g < 8; g++)
            #pragma unroll
            for (int j = 0; j < 4; j++) {
                int col = g * 128 + lane * 4 + j;
                if (v[g*4+j] > vm) { vm = v[g*4+j]; va = col; }
            }
        #pragma unroll
        for (int off = 16; off; off >>= 1) {
            float ov = __shfl_xor_sync(0xffffffffu, vm, off);
            int   oa = __shfl_xor_sync(0xffffffffu, va, off);
            if (ov > vm || (ov == vm && oa < va)) { vm = ov; va = oa; }
        }

        // candidate collection (cols within MARGIN of noisy max)
        if (lane == 0) scnt[wid] = 0;
        __syncwarp();
        const float thresh = vm - MARGIN;
        #pragma unroll
        for (int t = 0; t < 32; t++) {
            if (v[t] >= thresh) {
                int col = (t >> 2) * 128 + lane * 4 + (t & 3);
                int pos = atomicAdd(&scnt[wid], 1);
                if (pos < 30) scols[wid][pos] = col;
            }
        }
        __syncwarp();
        const int ncand = scnt[wid];

        // softmax (noisy logits -> avg_p; diversity tolerance absorbs noise)
        float sum = 0.0f;
        #pragma unroll
        for (int t = 0; t < 32; t++) { v[t] = __expf(v[t] - vm); sum += v[t]; }
        #pragma unroll
        for (int off = 16; off; off >>= 1)
            sum += __shfl_xor_sync(0xffffffffu, sum, off);
        float inv = 1.0f / sum;
        #pragma unroll
        for (int t = 0; t < 32; t++) pacc[t] += v[t] * inv;

        if (ncand <= 1) {
            // unambiguous: argmax exact; write m + z_q
            if (lane == 0) out[(size_t)B * EDIM + grow] = (float)va;
            const float4* cbr = (const float4*)(cb + (size_t)va * EDIM);
            float4* zo = (float4*)(out + (size_t)grow * EDIM);
            zo[lane]      = cbr[lane];
            zo[lane + 32] = cbr[lane + 32];
        } else {
            // ambiguous: enqueue for fp32 refinement
            int wi;
            if (lane == 0) {
                wi = atomicAdd(&g_nambig, 1);
                g_amb[wi][0] = grow;
                g_amb[wi][1] = ncand;
            }
            wi = __shfl_sync(0xffffffffu, wi, 0);
            int nlim = ncand < 30 ? ncand : 30;
            if (lane < nlim) g_amb[wi][2 + lane] = scols[wid][lane];
        }
    }

    #pragma unroll
    for (int t = 0; t < 32; t++) {
        int col = (t >> 2) * 128 + lane * 4 + (t & 3);
        atomicAdd(&savgp[col], pacc[t]);
    }
    __syncthreads();
    for (int c = tid; c < KDIM; c += 256)
        atomicAdd(&g_avgp[c], savgp[c]);

    // diversity finisher (last block) + scratch restore
    __threadfence();
    if (tid == 0) {
        unsigned int old = atomicAdd(&g_count, 1u);
        sIsLast = (old == gridDim.x - 1) ? 1 : 0;
    }
    __syncthreads();
    if (sIsLast) {
        const float invB = 1.0f / (float)B;
        const float logK = logf((float)KDIM);
        float sdiv = 0.0f;
        for (int c = tid; c < KDIM; c += 256) {
            float p = g_avgp[c] * invB;
            sdiv += p * (logf(fmaxf(p, 1e-9f)) + logK);
            g_avgp[c] = 0.0f;
        }
        #pragma unroll
        for (int off = 16; off; off >>= 1)
            sdiv += __shfl_xor_sync(0xffffffffu, sdiv, off);
        if (lane == 0) sred[wid] = sdiv;
        __syncthreads();
        if (tid == 0) {
            float t = 0.0f;
            #pragma unroll
            for (int w = 0; w < 8; w++) t += sred[w];
            size_t base = (size_t)B * EDIM + B;
            out[base]     = t;
            out[base + 1] = 0.0f;
            g_count = 0u;
        }
    }

    CLUSTER_SYNC();
}

// ---------------- fp32 refinement for ambiguous rows ----------------
__global__ __launch_bounds__(256)
void refine_kernel(const float* __restrict__ x, const float* __restrict__ W,
                   const float* __restrict__ bias, const float* __restrict__ gum,
                   const float* __restrict__ cb, float* __restrict__ out, int B)
{
    const int lane = threadIdx.x & 31;
    const int gwarp = (blockIdx.x * blockDim.x + threadIdx.x) >> 5;
    const int nwarps = (gridDim.x * blockDim.x) >> 5;
    const int n = g_nambig;

    for (int e = gwarp; e < n; e += nwarps) {
        const int row = g_amb[e][0];
        const int nc  = g_amb[e][1];
        const float* xr = x + (size_t)row * NIN;
        float best = -1e30f; int bestc = KDIM;

        if (nc <= 30) {
            for (int t = 0; t < nc; t++) {
                int c = g_amb[e][2 + t];
                const float* wr = W + (size_t)c * NIN;
                float s = 0.0f;
                #pragma unroll 8
                for (int i = lane; i < NIN; i += 32) s += xr[i] * wr[i];
                #pragma unroll
                for (int off = 16; off; off >>= 1)
                    s += __shfl_xor_sync(0xffffffffu, s, off);
                float val = s + bias[c] + gum[(size_t)row * KDIM + c];
                if (val > best || (val == best && c < bestc)) { best = val; bestc = c; }
            }
        } else {
            for (int c = 0; c < KDIM; c++) {
                const float* wr = W + (size_t)c * NIN;
                float s = 0.0f;
                #pragma unroll 8
                for (int i = lane; i < NIN; i += 32) s += xr[i] * wr[i];
                #pragma unroll
                for (int off = 16; off; off >>= 1)
                    s += __shfl_xor_sync(0xffffffffu, s, off);
                float val = s + bias[c] + gum[(size_t)row * KDIM + c];
                if (val > best) { best = val; bestc = c; }
            }
        }

        if (lane == 0) out[(size_t)B * EDIM + row] = (float)bestc;
        const float4* cbr = (const float4*)(cb + (size_t)bestc * EDIM);
        float4* zo = (float4*)(out + (size_t)row * EDIM);
        zo[lane]      = cbr[lane];
        zo[lane + 32] = cbr[lane + 32];
    }
}

// ---------------- launch ----------------
extern "C" void kernel_launch(void* const* d_in, const int* in_sizes, int n_in,
                              void* d_out, int out_size) {
    const float* x    = (const float*)d_in[0];
    const float* gum  = (const float*)d_in[1];
    const float* W    = (const float*)d_in[2];
    const float* bias = (const float*)d_in[3];
    const float* cb   = (const float*)d_in[4];
    float* out = (float*)d_out;

    const int B = in_sizes[0] / NIN;             // 65536

    cudaFuncSetAttribute(fused_vq_kernel, cudaFuncAttributeMaxDynamicSharedMemorySize, SMEM_DYN);

    rearr_x_kernel<<<B / BM, 256>>>(x);
    rearr_w_kernel<<<NKIT, 256>>>(W);
    fused_vq_kernel<<<B / BM, 256, SMEM_DYN>>>(gum, bias, cb, out, B);
    refine_kernel<<<128, 256>>>(x, W, bias, gum, cb, out, B);
}

// round 6
// speedup vs baseline: 40.7965x; 1.1735x over previous
#include <cuda_runtime.h>
#include <cuda_bf16.h>
#include <math.h>
#include <stdint.h>

#define NIN   1024
#define KDIM  1024
#define EDIM  256
#define BM    32
#define NKIT  64                       // K/16
#define ASLAB 1024                     // 32 rows x 32B bf16 per kchunk
#define WSLAB 32768                    // 1024 ko x 32B bf16 per kchunk
#define STAGE (ASLAB + WSLAB)          // 33792
#define NSTAGE 4
#define SMEM_DYN (NSTAGE * STAGE)      // 135168
#define NTHREADS 512
#define NWARP 16
#define MARGIN 0.03f

// ---------------- device scratch ----------------
__device__ __align__(128) unsigned char g_xs[(size_t)2048 * 64 * ASLAB];  // 134MB
__device__ __align__(128) unsigned char g_ws[(size_t)64 * WSLAB];         // 2MB
__device__ float g_avgp[KDIM];
__device__ unsigned int g_count;
__device__ int g_nambig;
__device__ int g_amb[65536][12];       // [0]=row [1]=n [2..9]=cols

// ---------------- PTX helpers ----------------
__device__ __forceinline__ uint32_t smem_u32(const void* p) {
    uint32_t a;
    asm("{ .reg .u64 t; cvta.to.shared.u64 t, %1; cvt.u32.u64 %0, t; }" : "=r"(a) : "l"(p));
    return a;
}
__device__ __forceinline__ uint32_t cluster_rank() {
    uint32_t r; asm("mov.u32 %0, %%cluster_ctarank;" : "=r"(r)); return r;
}
#define MBAR_INIT(a, n) \
    asm volatile("mbarrier.init.shared.b64 [%0], %1;" :: "r"(a), "r"((uint32_t)(n)) : "memory")
#define MBAR_EXPECT_TX(a, b) \
    asm volatile("mbarrier.arrive.expect_tx.shared.b64 _, [%0], %1;" :: "r"(a), "r"((uint32_t)(b)) : "memory")
#define MBAR_ARRIVE_RANK(a, rk) \
    asm volatile("{ .reg .b32 ra; mapa.shared::cluster.u32 ra, %0, %1; " \
                 "mbarrier.arrive.shared::cluster.b64 _, [ra]; }" :: "r"(a), "r"(rk) : "memory")
#define MBAR_WAIT(a, p) do { \
    uint32_t _m = (a); uint32_t _p = (p); uint32_t _d; \
    asm volatile("{\n\t.reg .pred q;\n\tmbarrier.try_wait.parity.acquire.cta.shared::cta.b64 q, [%1], %2;\n\tselp.b32 %0,1,0,q;\n\t}" \
        : "=r"(_d) : "r"(_m), "r"(_p) : "memory"); \
    if (!_d) { \
        asm volatile("{\n\t.reg .pred Q;\n\tWL_%=:\n\tmbarrier.try_wait.parity.acquire.cta.shared::cta.b64 Q, [%0], %1, 0x989680;\n\t@Q bra.uni WD_%=;\n\tbra.uni WL_%=;\n\tWD_%=:\n\t}" \
            :: "r"(_m), "r"(_p) : "memory"); \
    } } while (0)
#define CLUSTER_SYNC() do { \
    asm volatile("barrier.cluster.arrive.aligned;" ::: "memory"); \
    asm volatile("barrier.cluster.wait.aligned;" ::: "memory"); } while (0)

__device__ __forceinline__ void bulk_g2s(uint32_t dst, const void* src, uint32_t bytes, uint32_t mbar) {
    asm volatile("cp.async.bulk.shared::cluster.global.mbarrier::complete_tx::bytes [%0], [%1], %2, [%3];"
        :: "r"(dst), "l"(src), "r"(bytes), "r"(mbar) : "memory");
}
__device__ __forceinline__ void bulk_g2s_mc(uint32_t dst, const void* src, uint32_t bytes, uint32_t mbar, uint16_t mask) {
    asm volatile("cp.async.bulk.shared::cluster.global.mbarrier::complete_tx::bytes.multicast::cluster [%0], [%1], %2, [%3], %4;"
        :: "r"(dst), "l"(src), "r"(bytes), "r"(mbar), "h"(mask) : "memory");
}

__device__ __forceinline__ void mma_bf16(float d[4], uint32_t a0, uint32_t a1, uint32_t a2, uint32_t a3,
                                         uint32_t b0, uint32_t b1) {
    asm volatile(
        "mma.sync.aligned.m16n8k16.row.col.f32.bf16.bf16.f32 "
        "{%0,%1,%2,%3}, {%4,%5,%6,%7}, {%8,%9}, {%0,%1,%2,%3};"
        : "+f"(d[0]), "+f"(d[1]), "+f"(d[2]), "+f"(d[3])
        : "r"(a0), "r"(a1), "r"(a2), "r"(a3), "r"(b0), "r"(b1));
}

__device__ __forceinline__ uint32_t packbf2(float lo, float hi) {
    __nv_bfloat162 h = __floats2bfloat162_rn(lo, hi);
    return *(uint32_t*)&h;
}
// slot s (0..7) within a kchunk row holds k-pair c = (s>>1) + (s&1)*4
__device__ __forceinline__ int kperm(int c) { return (c & 3) * 2 + (c >> 2); }

// ---------------- rearrange x: smem-staged, both sides coalesced ----------------
__global__ __launch_bounds__(256) void rearr_x_kernel(const float* __restrict__ x) {
    __shared__ float sx[32 * 256];
    const int tid = threadIdx.x;
    const int rt  = blockIdx.x;
    unsigned char* dstbase = g_xs + (size_t)rt * 64 * ASLAB;
    for (int p = 0; p < 4; p++) {
        // load 32 rows x 256 floats, coalesced
        #pragma unroll
        for (int it = 0; it < 8; it++) {
            int o = it * 256 + tid;            // float4 index
            int r = o >> 6, c4 = o & 63;
            *(float4*)&sx[r * 256 + c4 * 4] =
                *(const float4*)(x + (size_t)(rt * 32 + r) * NIN + p * 256 + c4 * 4);
        }
        __syncthreads();
        // write 16 kchunks x 32 rows x 32B, coalesced uint4
        #pragma unroll
        for (int it = 0; it < 4; it++) {
            int g = it * 256 + tid;            // uint4 index
            int rowidx = g >> 1, half = g & 1;
            int kcl = rowidx >> 5, r = rowidx & 31;
            uint32_t v[4];
            #pragma unroll
            for (int t = 0; t < 4; t++) {
                int s = half * 4 + t;
                int c = (s >> 1) + (s & 1) * 4;
                const float* f = &sx[r * 256 + kcl * 16 + c * 2];
                v[t] = packbf2(f[0], f[1]);
            }
            *(uint4*)(dstbase + ((size_t)(p * 16 + kcl) * 32 + r) * 32 + half * 16) =
                make_uint4(v[0], v[1], v[2], v[3]);
        }
        __syncthreads();
    }
}
// g_ws: [kchunk 64][ko 1024][8 u32 slots]
__global__ __launch_bounds__(256) void rearr_w_kernel(const float* __restrict__ W) {
    const int tid = threadIdx.x;
    const int kchunk = blockIdx.x;
    if (kchunk == 0 && tid == 0) g_nambig = 0;
    uint32_t* dst = (uint32_t*)(g_ws + (size_t)kchunk * WSLAB);
    for (int it = 0; it < 16; it++) {
        int o  = it * 256 + tid;
        int ko = o >> 2, c4 = o & 3;
        float4 v = *(const float4*)(W + (size_t)ko * NIN + kchunk * 16 + c4 * 4);
        uint32_t* row = dst + ko * 8;
        row[kperm(2 * c4)]     = packbf2(v.x, v.y);
        row[kperm(2 * c4 + 1)] = packbf2(v.z, v.w);
    }
}

// ---------------- fused bf16 GEMM + register epilogue ----------------
__global__ __launch_bounds__(NTHREADS, 1) __cluster_dims__(2, 1, 1)
void fused_vq_kernel(const float* __restrict__ gum, const float* __restrict__ bias,
                     const float* __restrict__ cb, float* __restrict__ out, int B)
{
    extern __shared__ __align__(128) unsigned char smem[];
    __shared__ __align__(8) unsigned long long mb_full[NSTAGE], mb_empty[NSTAGE];
    __shared__ float swmax[NWARP][32];
    __shared__ int   swarg[NWARP][32];
    __shared__ float swsum[NWARP][32];
    __shared__ float frow[32], finv[32];
    __shared__ int   farg[32], rowcnt[32], srowm[32];
    __shared__ int   rowcols[32][8];
    __shared__ float sred[NWARP];
    __shared__ int   sIsLast;

    const int tid  = threadIdx.x;
    const int wid  = tid >> 5;
    const int lane = tid & 31;
    const int r0   = lane >> 2;
    const int q    = lane & 3;
    const uint32_t rank = cluster_rank();
    const int rowbase = blockIdx.x * BM;
    const int wbase   = wid * 64;

    const uint32_t smem_b = smem_u32(smem);
    uint32_t full_a[NSTAGE], empty_a[NSTAGE];
    #pragma unroll
    for (int s = 0; s < NSTAGE; s++) {
        full_a[s]  = smem_u32(&mb_full[s]);
        empty_a[s] = smem_u32(&mb_empty[s]);
    }
    if (tid == 0) {
        #pragma unroll
        for (int s = 0; s < NSTAGE; s++) { MBAR_INIT(full_a[s], 1); MBAR_INIT(empty_a[s], 2); }
    }
    __syncthreads();
    CLUSTER_SYNC();

    const unsigned char* asrc = g_xs + (size_t)blockIdx.x * 64 * ASLAB;
    const unsigned char* wsrc = g_ws + rank * (WSLAB / 2);

    if (tid == 0) {
        #pragma unroll
        for (int i = 0; i < NSTAGE; i++) {
            MBAR_EXPECT_TX(full_a[i], STAGE);
            bulk_g2s(smem_b + i * STAGE, asrc + (size_t)i * ASLAB, ASLAB, full_a[i]);
            bulk_g2s_mc(smem_b + i * STAGE + ASLAB + rank * (WSLAB / 2),
                        wsrc + (size_t)i * WSLAB, WSLAB / 2, full_a[i], (uint16_t)0x3);
        }
    }

    float d[2][8][4];
    #pragma unroll
    for (int m = 0; m < 2; m++)
        #pragma unroll
        for (int j = 0; j < 8; j++)
            #pragma unroll
            for (int t = 0; t < 4; t++) d[m][j][t] = 0.0f;

    for (int i = 0; i < NKIT; i++) {
        const int s = i & (NSTAGE - 1);
        MBAR_WAIT(full_a[s], (i >> 2) & 1);
        const uint32_t* As = (const uint32_t*)(smem + s * STAGE);
        const uint32_t* Ws = (const uint32_t*)(smem + s * STAGE + ASLAB);

        uint2 a[2][2];
        #pragma unroll
        for (int mt = 0; mt < 2; mt++) {
            a[mt][0] = *(const uint2*)&As[(mt * 16 + r0) * 8 + 2 * q];
            a[mt][1] = *(const uint2*)&As[(mt * 16 + r0 + 8) * 8 + 2 * q];
        }
        #pragma unroll
        for (int j = 0; j < 8; j++) {
            uint2 b = *(const uint2*)&Ws[(wbase + j * 8 + r0) * 8 + 2 * q];
            mma_bf16(d[0][j], a[0][0].x, a[0][1].x, a[0][0].y, a[0][1].y, b.x, b.y);
            mma_bf16(d[1][j], a[1][0].x, a[1][1].x, a[1][0].y, a[1][1].y, b.x, b.y);
        }
        __syncthreads();
        if (tid == 0) {
            MBAR_ARRIVE_RANK(empty_a[s], 0);
            MBAR_ARRIVE_RANK(empty_a[s], 1);
            if (i + NSTAGE < NKIT) {
                MBAR_WAIT(empty_a[s], (i >> 2) & 1);
                MBAR_EXPECT_TX(full_a[s], STAGE);
                bulk_g2s(smem_b + s * STAGE, asrc + (size_t)(i + NSTAGE) * ASLAB, ASLAB, full_a[s]);
                bulk_g2s_mc(smem_b + s * STAGE + ASLAB + rank * (WSLAB / 2),
                            wsrc + (size_t)(i + NSTAGE) * WSLAB, WSLAB / 2, full_a[s], (uint16_t)0x3);
            }
        }
    }
    __syncthreads();

    // ---------------- register epilogue ----------------
    // rows held by this thread: r0 + row_i*8, row_i = mt*2 + hr
    // cols: wbase + j*8 + 2q + {0,1};  d[mt][j][hr*2+half]
    // 1) add bias+gumbel, per-row max/argmax
    float vmax[4]; int varg[4];
    #pragma unroll
    for (int row_i = 0; row_i < 4; row_i++) {
        const int grow = rowbase + r0 + row_i * 8;
        const int mt = row_i >> 1, hr = row_i & 1;
        float vm = -1e30f; int va = 0;
        #pragma unroll
        for (int j = 0; j < 8; j++) {
            const int col = wbase + j * 8 + 2 * q;
            float2 b2 = *(const float2*)(bias + col);
            float2 g2 = *(const float2*)(gum + (size_t)grow * KDIM + col);
            float v0 = d[mt][j][hr * 2 + 0] + b2.x + g2.x;
            float v1 = d[mt][j][hr * 2 + 1] + b2.y + g2.y;
            d[mt][j][hr * 2 + 0] = v0;
            d[mt][j][hr * 2 + 1] = v1;
            if (v0 > vm) { vm = v0; va = col; }
            if (v1 > vm) { vm = v1; va = col + 1; }
        }
        vmax[row_i] = vm; varg[row_i] = va;
    }
    #pragma unroll
    for (int off = 1; off <= 2; off <<= 1) {
        #pragma unroll
        for (int row_i = 0; row_i < 4; row_i++) {
            float ov = __shfl_xor_sync(0xffffffffu, vmax[row_i], off);
            int   oa = __shfl_xor_sync(0xffffffffu, varg[row_i], off);
            if (ov > vmax[row_i] || (ov == vmax[row_i] && oa < varg[row_i])) {
                vmax[row_i] = ov; varg[row_i] = oa;
            }
        }
    }
    if (q == 0) {
        #pragma unroll
        for (int row_i = 0; row_i < 4; row_i++) {
            swmax[wid][r0 + row_i * 8] = vmax[row_i];
            swarg[wid][r0 + row_i * 8] = varg[row_i];
        }
    }
    __syncthreads();
    if (tid < 32) {
        float best = -1e30f; int barg = KDIM;
        #pragma unroll
        for (int w = 0; w < NWARP; w++) {
            float v = swmax[w][tid]; int a = swarg[w][tid];
            if (v > best || (v == best && a < barg)) { best = v; barg = a; }
        }
        frow[tid] = best; farg[tid] = barg;
        rowcnt[tid] = 0; srowm[tid] = barg;
    }
    __syncthreads();

    // 2) candidates + exp in place + row partial sums
    float psum[4] = {0.f, 0.f, 0.f, 0.f};
    #pragma unroll
    for (int row_i = 0; row_i < 4; row_i++) {
        const int row = r0 + row_i * 8;
        const int mt = row_i >> 1, hr = row_i & 1;
        const float rm = frow[row];
        const float th = rm - MARGIN;
        #pragma unroll
        for (int j = 0; j < 8; j++) {
            #pragma unroll
            for (int half = 0; half < 2; half++) {
                float v = d[mt][j][hr * 2 + half];
                if (v >= th) {
                    int pos = atomicAdd(&rowcnt[row], 1);
                    if (pos < 8) rowcols[row][pos] = wbase + j * 8 + 2 * q + half;
                }
                float e = __expf(v - rm);
                d[mt][j][hr * 2 + half] = e;
                psum[row_i] += e;
            }
        }
    }
    #pragma unroll
    for (int off = 1; off <= 2; off <<= 1)
        #pragma unroll
        for (int row_i = 0; row_i < 4; row_i++)
            psum[row_i] += __shfl_xor_sync(0xffffffffu, psum[row_i], off);
    if (q == 0) {
        #pragma unroll
        for (int row_i = 0; row_i < 4; row_i++)
            swsum[wid][r0 + row_i * 8] = psum[row_i];
    }
    __syncthreads();
    if (tid < 32) {
        float s = 0.0f;
        #pragma unroll
        for (int w = 0; w < NWARP; w++) s += swsum[w][tid];
        finv[tid] = 1.0f / s;
        const int grow = rowbase + tid;
        out[(size_t)B * EDIM + grow] = (float)farg[tid];     // m (refined later if ambiguous)
        int n = rowcnt[tid];
        if (n > 1) {
            int wi = atomicAdd(&g_nambig, 1);
            g_amb[wi][0] = grow;
            g_amb[wi][1] = n;
            int nl = n < 8 ? n : 8;
            for (int t = 0; t < nl; t++) g_amb[wi][2 + t] = rowcols[tid][t];
        }
    }
    __syncthreads();

    // 3) avg_p: per-col sum over rows, reduce across r0 lanes, one atomic per col
    #pragma unroll
    for (int j = 0; j < 8; j++) {
        #pragma unroll
        for (int half = 0; half < 2; half++) {
            float t = 0.0f;
            #pragma unroll
            for (int row_i = 0; row_i < 4; row_i++) {
                const int mt = row_i >> 1, hr = row_i & 1;
                t += d[mt][j][hr * 2 + half] * finv[r0 + row_i * 8];
            }
            t += __shfl_xor_sync(0xffffffffu, t, 4);
            t += __shfl_xor_sync(0xffffffffu, t, 8);
            t += __shfl_xor_sync(0xffffffffu, t, 16);
            if (r0 == 0) atomicAdd(&g_avgp[wbase + j * 8 + 2 * q + half], t);
        }
    }

    // 4) z_q gather
    #pragma unroll
    for (int it = 0; it < 4; it++) {
        int idx = it * NTHREADS + tid;       // 0..2047
        int row = idx >> 6, v = idx & 63;
        int arg = srowm[row];
        float4 cv = *(const float4*)(cb + (size_t)arg * EDIM + v * 4);
        *(float4*)(out + (size_t)(rowbase + row) * EDIM + v * 4) = cv;
    }

    // 5) diversity finisher
    __threadfence();
    if (tid == 0) {
        unsigned int old = atomicAdd(&g_count, 1u);
        sIsLast = (old == gridDim.x - 1) ? 1 : 0;
    }
    __syncthreads();
    if (sIsLast) {
        const float invB = 1.0f / (float)B;
        const float logK = logf((float)KDIM);
        float sdiv = 0.0f;
        for (int c = tid; c < KDIM; c += NTHREADS) {
            float p = g_avgp[c] * invB;
            sdiv += p * (logf(fmaxf(p, 1e-9f)) + logK);
            g_avgp[c] = 0.0f;
        }
        #pragma unroll
        for (int off = 16; off; off >>= 1)
            sdiv += __shfl_xor_sync(0xffffffffu, sdiv, off);
        if (lane == 0) sred[wid] = sdiv;
        __syncthreads();
        if (tid == 0) {
            float t = 0.0f;
            #pragma unroll
            for (int w = 0; w < NWARP; w++) t += sred[w];
            size_t base = (size_t)B * EDIM + B;
            out[base]     = t;
            out[base + 1] = 0.0f;
            g_count = 0u;
        }
    }
    CLUSTER_SYNC();
}

// ---------------- fp32 refinement for ambiguous rows ----------------
__global__ __launch_bounds__(256)
void refine_kernel(const float* __restrict__ x, const float* __restrict__ W,
                   const float* __restrict__ bias, const float* __restrict__ gum,
                   const float* __restrict__ cb, float* __restrict__ out, int B)
{
    const int lane = threadIdx.x & 31;
    const int gwarp = (blockIdx.x * blockDim.x + threadIdx.x) >> 5;
    const int nwarps = (gridDim.x * blockDim.x) >> 5;
    const int n = g_nambig;

    for (int e = gwarp; e < n; e += nwarps) {
        const int row = g_amb[e][0];
        const int nc  = g_amb[e][1];
        const float* xr = x + (size_t)row * NIN;
        float best = -1e30f; int bestc = KDIM;

        if (nc <= 8) {
            for (int t = 0; t < nc; t++) {
                int c = g_amb[e][2 + t];
                const float* wr = W + (size_t)c * NIN;
                float s = 0.0f;
                #pragma unroll 8
                for (int i = lane; i < NIN; i += 32) s += xr[i] * wr[i];
                #pragma unroll
                for (int off = 16; off; off >>= 1)
                    s += __shfl_xor_sync(0xffffffffu, s, off);
                float val = s + bias[c] + gum[(size_t)row * KDIM + c];
                if (val > best || (val == best && c < bestc)) { best = val; bestc = c; }
            }
        } else {
            for (int c = 0; c < KDIM; c++) {
                const float* wr = W + (size_t)c * NIN;
                float s = 0.0f;
                #pragma unroll 8
                for (int i = lane; i < NIN; i += 32) s += xr[i] * wr[i];
                #pragma unroll
                for (int off = 16; off; off >>= 1)
                    s += __shfl_xor_sync(0xffffffffu, s, off);
                float val = s + bias[c] + gum[(size_t)row * KDIM + c];
                if (val > best) { best = val; bestc = c; }
            }
        }

        if (lane == 0) out[(size_t)B * EDIM + row] = (float)bestc;
        const float4* cbr = (const float4*)(cb + (size_t)bestc * EDIM);
        float4* zo = (float4*)(out + (size_t)row * EDIM);
        zo[lane]      = cbr[lane];
        zo[lane + 32] = cbr[lane + 32];
    }
}

// ---------------- launch ----------------
extern "C" void kernel_launch(void* const* d_in, const int* in_sizes, int n_in,
                              void* d_out, int out_size) {
    const float* x    = (const float*)d_in[0];
    const float* gum  = (const float*)d_in[1];
    const float* W    = (const float*)d_in[2];
    const float* bias = (const float*)d_in[3];
    const float* cb   = (const float*)d_in[4];
    float* out = (float*)d_out;

    const int B = in_sizes[0] / NIN;             // 65536

    cudaFuncSetAttribute(fused_vq_kernel, cudaFuncAttributeMaxDynamicSharedMemorySize, SMEM_DYN);

    rearr_x_kernel<<<B / BM, 256>>>(x);
    rearr_w_kernel<<<NKIT, 256>>>(W);
    fused_vq_kernel<<<B / BM, NTHREADS, SMEM_DYN>>>(gum, bias, cb, out, B);
    refine_kernel<<<256, 256>>>(x, W, bias, gum, cb, out, B);
}

// round 7
// speedup vs baseline: 46.8372x; 1.1481x over previous
#include <cuda_runtime.h>
#include <cuda_bf16.h>
#include <math.h>
#include <stdint.h>

#define NIN   1024
#define KDIM  1024
#define EDIM  256
#define BM    32
#define NPAIRS 1024                    // 2048 row-tiles as pairs
#define ASLAB 1024                     // 32 rows x 32B bf16 per kchunk
#define WSLAB 32768                    // 1024 ko x 32B bf16 per kchunk
#define ASTG  (2 * ASLAB)              // 2 kchunks per stage
#define WSTG  (2 * WSLAB)
#define STAGE (ASTG + WSTG)            // 67584
#define NSTAGE 3
#define SMEM_DYN (NSTAGE * STAGE)      // 202752
#define NTHREADS 512
#define NWARP 16
#define MARGIN 0.03f

// ---------------- device scratch ----------------
__device__ __align__(128) unsigned char g_xs[(size_t)2048 * 64 * ASLAB];  // 134MB
__device__ __align__(128) unsigned char g_ws[(size_t)64 * WSLAB];         // 2MB
__device__ float g_avgp[KDIM];
__device__ unsigned int g_count;

// ---------------- PTX helpers ----------------
__device__ __forceinline__ uint32_t smem_u32(const void* p) {
    uint32_t a;
    asm("{ .reg .u64 t; cvta.to.shared.u64 t, %1; cvt.u32.u64 %0, t; }" : "=r"(a) : "l"(p));
    return a;
}
__device__ __forceinline__ uint32_t cluster_rank() {
    uint32_t r; asm("mov.u32 %0, %%cluster_ctarank;" : "=r"(r)); return r;
}
#define MBAR_INIT(a, n) \
    asm volatile("mbarrier.init.shared.b64 [%0], %1;" :: "r"(a), "r"((uint32_t)(n)) : "memory")
#define MBAR_EXPECT_TX(a, b) \
    asm volatile("mbarrier.arrive.expect_tx.shared.b64 _, [%0], %1;" :: "r"(a), "r"((uint32_t)(b)) : "memory")
#define MBAR_ARRIVE_RANK(a, rk) \
    asm volatile("{ .reg .b32 ra; mapa.shared::cluster.u32 ra, %0, %1; " \
                 "mbarrier.arrive.shared::cluster.b64 _, [ra]; }" :: "r"(a), "r"(rk) : "memory")
#define MBAR_WAIT(a, p) do { \
    uint32_t _m = (a); uint32_t _p = (p); uint32_t _d; \
    asm volatile("{\n\t.reg .pred q;\n\tmbarrier.try_wait.parity.acquire.cta.shared::cta.b64 q, [%1], %2;\n\tselp.b32 %0,1,0,q;\n\t}" \
        : "=r"(_d) : "r"(_m), "r"(_p) : "memory"); \
    if (!_d) { \
        asm volatile("{\n\t.reg .pred Q;\n\tWL_%=:\n\tmbarrier.try_wait.parity.acquire.cta.shared::cta.b64 Q, [%0], %1, 0x989680;\n\t@Q bra.uni WD_%=;\n\tbra.uni WL_%=;\n\tWD_%=:\n\t}" \
            :: "r"(_m), "r"(_p) : "memory"); \
    } } while (0)
#define CLUSTER_SYNC() do { \
    asm volatile("barrier.cluster.arrive.aligned;" ::: "memory"); \
    asm volatile("barrier.cluster.wait.aligned;" ::: "memory"); } while (0)

__device__ __forceinline__ void bulk_g2s(uint32_t dst, const void* src, uint32_t bytes, uint32_t mbar) {
    asm volatile("cp.async.bulk.shared::cluster.global.mbarrier::complete_tx::bytes [%0], [%1], %2, [%3];"
        :: "r"(dst), "l"(src), "r"(bytes), "r"(mbar) : "memory");
}
__device__ __forceinline__ void bulk_g2s_mc(uint32_t dst, const void* src, uint32_t bytes, uint32_t mbar, uint16_t mask) {
    asm volatile("cp.async.bulk.shared::cluster.global.mbarrier::complete_tx::bytes.multicast::cluster [%0], [%1], %2, [%3], %4;"
        :: "r"(dst), "l"(src), "r"(bytes), "r"(mbar), "h"(mask) : "memory");
}

__device__ __forceinline__ void mma_bf16(float d[4], uint32_t a0, uint32_t a1, uint32_t a2, uint32_t a3,
                                         uint32_t b0, uint32_t b1) {
    asm volatile(
        "mma.sync.aligned.m16n8k16.row.col.f32.bf16.bf16.f32 "
        "{%0,%1,%2,%3}, {%4,%5,%6,%7}, {%8,%9}, {%0,%1,%2,%3};"
        : "+f"(d[0]), "+f"(d[1]), "+f"(d[2]), "+f"(d[3])
        : "r"(a0), "r"(a1), "r"(a2), "r"(a3), "r"(b0), "r"(b1));
}

__device__ __forceinline__ uint32_t packbf2(float lo, float hi) {
    __nv_bfloat162 h = __floats2bfloat162_rn(lo, hi);
    return *(uint32_t*)&h;
}
__device__ __forceinline__ int kperm(int c) { return (c & 3) * 2 + (c >> 2); }

// ---------------- rearrange x (smem staged, both sides coalesced) ----------------
__global__ __launch_bounds__(256) void rearr_x_kernel(const float* __restrict__ x) {
    __shared__ float sx[32 * 256];
    const int tid = threadIdx.x;
    const int rt  = blockIdx.x;
    unsigned char* dstbase = g_xs + (size_t)rt * 64 * ASLAB;
    for (int p = 0; p < 4; p++) {
        #pragma unroll
        for (int it = 0; it < 8; it++) {
            int o = it * 256 + tid;
            int r = o >> 6, c4 = o & 63;
            *(float4*)&sx[r * 256 + c4 * 4] =
                *(const float4*)(x + (size_t)(rt * 32 + r) * NIN + p * 256 + c4 * 4);
        }
        __syncthreads();
        #pragma unroll
        for (int it = 0; it < 4; it++) {
            int g = it * 256 + tid;
            int rowidx = g >> 1, half = g & 1;
            int kcl = rowidx >> 5, r = rowidx & 31;
            uint32_t v[4];
            #pragma unroll
            for (int t = 0; t < 4; t++) {
                int s = half * 4 + t;
                int c = (s >> 1) + (s & 1) * 4;
                const float* f = &sx[r * 256 + kcl * 16 + c * 2];
                v[t] = packbf2(f[0], f[1]);
            }
            *(uint4*)(dstbase + ((size_t)(p * 16 + kcl) * 32 + r) * 32 + half * 16) =
                make_uint4(v[0], v[1], v[2], v[3]);
        }
        __syncthreads();
    }
}
__global__ __launch_bounds__(256) void rearr_w_kernel(const float* __restrict__ W) {
    const int tid = threadIdx.x;
    const int kchunk = blockIdx.x;
    uint32_t* dst = (uint32_t*)(g_ws + (size_t)kchunk * WSLAB);
    for (int it = 0; it < 16; it++) {
        int o  = it * 256 + tid;
        int ko = o >> 2, c4 = o & 3;
        float4 v = *(const float4*)(W + (size_t)ko * NIN + kchunk * 16 + c4 * 4);
        uint32_t* row = dst + ko * 8;
        row[kperm(2 * c4)]     = packbf2(v.x, v.y);
        row[kperm(2 * c4 + 1)] = packbf2(v.z, v.w);
    }
}

// ---------------- persistent fused GEMM + epilogue + inline refine ----------------
__global__ __launch_bounds__(NTHREADS, 1) __cluster_dims__(2, 1, 1)
void fused_vq_kernel(const float* __restrict__ x, const float* __restrict__ W,
                     const float* __restrict__ gum, const float* __restrict__ bias,
                     const float* __restrict__ cb, float* __restrict__ out, int B)
{
    extern __shared__ __align__(128) unsigned char smem[];
    __shared__ __align__(8) unsigned long long mb_full[NSTAGE], mb_empty[NSTAGE];
    __shared__ float swmax[NWARP][32];
    __shared__ int   swarg[NWARP][32];
    __shared__ float swsum[NWARP][32];
    __shared__ float frow[32], finv[32];
    __shared__ int   rowcnt[32], srowm[32];
    __shared__ int   rowcols[32][8];
    __shared__ int   s_amblist[32];
    __shared__ int   s_namb;
    __shared__ float sred[NWARP];
    __shared__ int   sIsLast;

    const int tid  = threadIdx.x;
    const int wid  = tid >> 5;
    const int lane = tid & 31;
    const int r0   = lane >> 2;
    const int q    = lane & 3;
    const uint32_t rank = cluster_rank();
    const int cl   = blockIdx.x >> 1;
    const int ncl  = gridDim.x >> 1;
    const int wbase = wid * 64;

    const int ntiles = (NPAIRS - 1 - cl) / ncl + 1;    // pairs: cl, cl+ncl, ...
    const int total_its = ntiles * 32;

    const uint32_t smem_b = smem_u32(smem);
    uint32_t full_a[NSTAGE], empty_a[NSTAGE];
    #pragma unroll
    for (int s = 0; s < NSTAGE; s++) {
        full_a[s]  = smem_u32(&mb_full[s]);
        empty_a[s] = smem_u32(&mb_empty[s]);
    }
    if (tid == 0) {
        #pragma unroll
        for (int s = 0; s < NSTAGE; s++) { MBAR_INIT(full_a[s], 1); MBAR_INIT(empty_a[s], 2); }
    }
    __syncthreads();
    CLUSTER_SYNC();

    // prologue: fill 3 stages (first 6 kchunks of first tile)
    if (tid == 0) {
        #pragma unroll
        for (int i = 0; i < NSTAGE; i++) {
            MBAR_EXPECT_TX(full_a[i], STAGE);
            bulk_g2s(smem_b + i * STAGE,
                     g_xs + ((size_t)(2 * cl + rank) * 64 + 2 * i) * ASLAB, ASTG, full_a[i]);
            bulk_g2s_mc(smem_b + i * STAGE + ASTG + rank * WSLAB,
                        g_ws + (size_t)(2 * i + rank) * WSLAB, WSLAB, full_a[i], (uint16_t)0x3);
        }
    }

    int it = 0, s = 0, ph = 0;
    for (int t = 0; t < ntiles; t++) {
        const int p = cl + t * ncl;
        const int rowbase = (2 * p + rank) * BM;

        float d[2][8][4];
        #pragma unroll
        for (int m = 0; m < 2; m++)
            #pragma unroll
            for (int j = 0; j < 8; j++)
                #pragma unroll
                for (int v = 0; v < 4; v++) d[m][j][v] = 0.0f;

        // -------- mainloop: 32 stage-iters x 2 kchunks --------
        for (int g = 0; g < 32; g++) {
            MBAR_WAIT(full_a[s], ph);
            const uint32_t* base = (const uint32_t*)(smem + s * STAGE);
            #pragma unroll
            for (int kc = 0; kc < 2; kc++) {
                const uint32_t* As = base + kc * (ASLAB / 4);
                const uint32_t* Ws = base + (ASTG / 4) + kc * (WSLAB / 4);
                uint2 a[2][2];
                #pragma unroll
                for (int mt = 0; mt < 2; mt++) {
                    a[mt][0] = *(const uint2*)&As[(mt * 16 + r0) * 8 + 2 * q];
                    a[mt][1] = *(const uint2*)&As[(mt * 16 + r0 + 8) * 8 + 2 * q];
                }
                #pragma unroll
                for (int j = 0; j < 8; j++) {
                    uint2 b = *(const uint2*)&Ws[(wbase + j * 8 + r0) * 8 + 2 * q];
                    mma_bf16(d[0][j], a[0][0].x, a[0][1].x, a[0][0].y, a[0][1].y, b.x, b.y);
                    mma_bf16(d[1][j], a[1][0].x, a[1][1].x, a[1][0].y, a[1][1].y, b.x, b.y);
                }
            }
            __syncthreads();
            if (tid == 0) {
                MBAR_ARRIVE_RANK(empty_a[s], 0);
                MBAR_ARRIVE_RANK(empty_a[s], 1);
                const int git = it + NSTAGE;
                if (git < total_its) {
                    const int pi = git >> 5, gg = git & 31;
                    const int pp = cl + pi * ncl;
                    MBAR_WAIT(empty_a[s], ph);
                    MBAR_EXPECT_TX(full_a[s], STAGE);
                    bulk_g2s(smem_b + s * STAGE,
                             g_xs + ((size_t)(2 * pp + rank) * 64 + 2 * gg) * ASLAB, ASTG, full_a[s]);
                    bulk_g2s_mc(smem_b + s * STAGE + ASTG + rank * WSLAB,
                                g_ws + (size_t)(2 * gg + rank) * WSLAB, WSLAB, full_a[s], (uint16_t)0x3);
                }
            }
            it++; s++; if (s == NSTAGE) { s = 0; ph ^= 1; }
        }

        // -------- epilogue --------
        // step 1: + bias + gumbel; per-thread row max/arg
        float vmax[4]; int varg[4];
        #pragma unroll
        for (int row_i = 0; row_i < 4; row_i++) {
            const int grow = rowbase + r0 + row_i * 8;
            const int mt = row_i >> 1, hr = row_i & 1;
            float vm = -1e30f; int va = 0;
            #pragma unroll
            for (int j = 0; j < 8; j++) {
                const int col = wbase + j * 8 + 2 * q;
                float2 b2 = *(const float2*)(bias + col);
                float2 g2 = *(const float2*)(gum + (size_t)grow * KDIM + col);
                float v0 = d[mt][j][hr * 2 + 0] + b2.x + g2.x;
                float v1 = d[mt][j][hr * 2 + 1] + b2.y + g2.y;
                d[mt][j][hr * 2 + 0] = v0;
                d[mt][j][hr * 2 + 1] = v1;
                if (v0 > vm) { vm = v0; va = col; }
                if (v1 > vm) { vm = v1; va = col + 1; }
            }
            vmax[row_i] = vm; varg[row_i] = va;
        }
        #pragma unroll
        for (int off = 1; off <= 2; off <<= 1)
            #pragma unroll
            for (int row_i = 0; row_i < 4; row_i++) {
                float ov = __shfl_xor_sync(0xffffffffu, vmax[row_i], off);
                int   oa = __shfl_xor_sync(0xffffffffu, varg[row_i], off);
                if (ov > vmax[row_i] || (ov == vmax[row_i] && oa < varg[row_i])) {
                    vmax[row_i] = ov; varg[row_i] = oa;
                }
            }
        if (q == 0) {
            #pragma unroll
            for (int row_i = 0; row_i < 4; row_i++) {
                swmax[wid][r0 + row_i * 8] = vmax[row_i];
                swarg[wid][r0 + row_i * 8] = varg[row_i];
            }
        }
        __syncthreads();
        // step 2: combine to per-row max/arg
        if (tid < 32) {
            float best = -1e30f; int barg = KDIM;
            #pragma unroll
            for (int w = 0; w < NWARP; w++) {
                float v = swmax[w][tid]; int a = swarg[w][tid];
                if (v > best || (v == best && a < barg)) { best = v; barg = a; }
            }
            frow[tid] = best; srowm[tid] = barg; rowcnt[tid] = 0;
            if (tid == 0) s_namb = 0;
        }
        __syncthreads();
        // step 3: candidates + exp in place + row partial sums
        float psum[4] = {0.f, 0.f, 0.f, 0.f};
        #pragma unroll
        for (int row_i = 0; row_i < 4; row_i++) {
            const int row = r0 + row_i * 8;
            const int mt = row_i >> 1, hr = row_i & 1;
            const float rm = frow[row];
            const float th = rm - MARGIN;
            #pragma unroll
            for (int j = 0; j < 8; j++) {
                #pragma unroll
                for (int half = 0; half < 2; half++) {
                    float v = d[mt][j][hr * 2 + half];
                    if (v >= th) {
                        int pos = atomicAdd(&rowcnt[row], 1);
                        if (pos < 8) rowcols[row][pos] = wbase + j * 8 + 2 * q + half;
                    }
                    float e = __expf(v - rm);
                    d[mt][j][hr * 2 + half] = e;
                    psum[row_i] += e;
                }
            }
        }
        #pragma unroll
        for (int off = 1; off <= 2; off <<= 1)
            #pragma unroll
            for (int row_i = 0; row_i < 4; row_i++)
                psum[row_i] += __shfl_xor_sync(0xffffffffu, psum[row_i], off);
        if (q == 0) {
            #pragma unroll
            for (int row_i = 0; row_i < 4; row_i++)
                swsum[wid][r0 + row_i * 8] = psum[row_i];
        }
        __syncthreads();
        // step 4: row inv-sums; enlist ambiguous rows
        if (tid < 32) {
            float sm = 0.0f;
            #pragma unroll
            for (int w = 0; w < NWARP; w++) sm += swsum[w][tid];
            finv[tid] = 1.0f / sm;
            if (rowcnt[tid] > 1) {
                int ix = atomicAdd(&s_namb, 1);
                s_amblist[ix] = tid;
            }
        }
        __syncthreads();
        // step 5: avg_p reduce + atomics
        #pragma unroll
        for (int j = 0; j < 8; j++) {
            #pragma unroll
            for (int half = 0; half < 2; half++) {
                float tt = 0.0f;
                #pragma unroll
                for (int row_i = 0; row_i < 4; row_i++) {
                    const int mt = row_i >> 1, hr = row_i & 1;
                    tt += d[mt][j][hr * 2 + half] * finv[r0 + row_i * 8];
                }
                tt += __shfl_xor_sync(0xffffffffu, tt, 4);
                tt += __shfl_xor_sync(0xffffffffu, tt, 8);
                tt += __shfl_xor_sync(0xffffffffu, tt, 16);
                if (r0 == 0) atomicAdd(&g_avgp[wbase + j * 8 + 2 * q + half], tt);
            }
        }
        // step 6: inline fp32 refinement (warp per ambiguous row)
        const int na = s_namb;
        for (int a = wid; a < na; a += NWARP) {
            const int row = s_amblist[a];
            const int nc  = rowcnt[row];
            const int grow = rowbase + row;
            const float* xr = x + (size_t)grow * NIN;
            float xv[32];
            #pragma unroll
            for (int u = 0; u < 32; u++) xv[u] = xr[lane + u * 32];
            float best = -1e30f; int bestc = KDIM;
            if (nc <= 8) {
                for (int ti = 0; ti < nc; ti++) {
                    const int c = rowcols[row][ti];
                    const float* wr = W + (size_t)c * NIN;
                    float sm = 0.0f;
                    #pragma unroll
                    for (int u = 0; u < 32; u++) sm = fmaf(xv[u], wr[lane + u * 32], sm);
                    #pragma unroll
                    for (int off = 16; off; off >>= 1)
                        sm += __shfl_xor_sync(0xffffffffu, sm, off);
                    float val = sm + bias[c] + gum[(size_t)grow * KDIM + c];
                    if (val > best || (val == best && c < bestc)) { best = val; bestc = c; }
                }
            } else {
                for (int c = 0; c < KDIM; c++) {
                    const float* wr = W + (size_t)c * NIN;
                    float sm = 0.0f;
                    #pragma unroll
                    for (int u = 0; u < 32; u++) sm = fmaf(xv[u], wr[lane + u * 32], sm);
                    #pragma unroll
                    for (int off = 16; off; off >>= 1)
                        sm += __shfl_xor_sync(0xffffffffu, sm, off);
                    float val = sm + bias[c] + gum[(size_t)grow * KDIM + c];
                    if (val > best) { best = val; bestc = c; }
                }
            }
            if (lane == 0) srowm[row] = bestc;
        }
        __syncthreads();
        // step 7: m + z_q
        if (tid < 32) out[(size_t)B * EDIM + rowbase + tid] = (float)srowm[tid];
        #pragma unroll
        for (int g2 = 0; g2 < 4; g2++) {
            int idx = g2 * NTHREADS + tid;     // 0..2047
            int row = idx >> 6, v = idx & 63;
            int arg = srowm[row];
            float4 cv = *(const float4*)(cb + (size_t)arg * EDIM + v * 4);
            *(float4*)(out + (size_t)(rowbase + row) * EDIM + v * 4) = cv;
        }
        __syncthreads();
    }

    // -------- diversity finisher --------
    __threadfence();
    if (tid == 0) {
        unsigned int old = atomicAdd(&g_count, 1u);
        sIsLast = (old == gridDim.x - 1) ? 1 : 0;
    }
    __syncthreads();
    if (sIsLast) {
        const float invB = 1.0f / (float)B;
        const float logK = logf((float)KDIM);
        float sdiv = 0.0f;
        for (int c = tid; c < KDIM; c += NTHREADS) {
            float p2 = g_avgp[c] * invB;
            sdiv += p2 * (logf(fmaxf(p2, 1e-9f)) + logK);
            g_avgp[c] = 0.0f;
        }
        #pragma unroll
        for (int off = 16; off; off >>= 1)
            sdiv += __shfl_xor_sync(0xffffffffu, sdiv, off);
        if (lane == 0) sred[wid] = sdiv;
        __syncthreads();
        if (tid == 0) {
            float tt = 0.0f;
            #pragma unroll
            for (int w = 0; w < NWARP; w++) tt += sred[w];
            size_t base = (size_t)B * EDIM + B;
            out[base]     = tt;
            out[base + 1] = 0.0f;
            g_count = 0u;
        }
    }
    CLUSTER_SYNC();
}

// ---------------- launch ----------------
extern "C" void kernel_launch(void* const* d_in, const int* in_sizes, int n_in,
                              void* d_out, int out_size) {
    const float* x    = (const float*)d_in[0];
    const float* gum  = (const float*)d_in[1];
    const float* W    = (const float*)d_in[2];
    const float* bias = (const float*)d_in[3];
    const float* cb   = (const float*)d_in[4];
    float* out = (float*)d_out;

    const int B = in_sizes[0] / NIN;             // 65536

    static int nsm = 0;
    if (nsm == 0) {
        cudaDeviceGetAttribute(&nsm, cudaDevAttrMultiProcessorCount, 0);
        nsm &= ~1;                                // even, cluster of 2
        if (nsm <= 0) nsm = 148;
        cudaFuncSetAttribute(fused_vq_kernel, cudaFuncAttributeMaxDynamicSharedMemorySize, SMEM_DYN);
    }

    rearr_x_kernel<<<B / BM, 256>>>(x);
    rearr_w_kernel<<<64, 256>>>(W);
    fused_vq_kernel<<<nsm, NTHREADS, SMEM_DYN>>>(x, W, gum, bias, cb, out, B);
}